// round 8
// baseline (speedup 1.0000x reference)
#include <cuda_runtime.h>
#include <math.h>
#include <stdint.h>

// Problem dims
#define B 32
#define S 256
#define EHID 768
#define DHID 128
#define EMBD 200
#define VOC 32000
#define TT 96
#define NSTEP 95
#define KFC 1096    // DHID + EHID + EMBD
#define KLSTM 968   // EMBD + EHID

typedef unsigned long long ull;

// Scratch (static device globals: allowed; no runtime allocation)
__device__ float g_fcwt[(size_t)KFC * VOC];   // fc_W transposed: [k][v], ~140MB
__device__ float g_enc_proj[B * S * DHID];    // 4MB, step-invariant attention term
__device__ float g_xcatT[KFC * B];            // FC input, transposed [k][b]
__device__ float g_attw[B * S];               // softmax attention weights
__device__ float g_h[2][B * DHID];            // ping-pong across steps
__device__ float g_c[B * DHID];

// fast activations (validated: rel_err stays ~7e-7)
__device__ __forceinline__ float sigfast(float x) {
    return __fdividef(1.0f, 1.0f + __expf(-x));
}
__device__ __forceinline__ float tanhfast(float x) {
    x = fminf(fmaxf(x, -15.0f), 15.0f);
    float e = __expf(2.0f * x);
    return __fdividef(e - 1.0f, e + 1.0f);
}

// cp.async helpers
__device__ __forceinline__ void cpasync16(uint32_t dst, const void* src) {
    asm volatile("cp.async.cg.shared.global [%0], [%1], 16;" :: "r"(dst), "l"(src));
}
__device__ __forceinline__ void cpcommit() {
    asm volatile("cp.async.commit_group;" ::: "memory");
}
template <int N> __device__ __forceinline__ void cpwait() {
    asm volatile("cp.async.wait_group %0;" :: "n"(N) : "memory");
}

// packed fp32x2 (dual-pipe FFMA2; w pairs come free from smem layout)
__device__ __forceinline__ ull pk2(float lo, float hi) {
    ull r; asm("mov.b64 %0, {%1, %2};" : "=l"(r) : "f"(lo), "f"(hi)); return r;
}
__device__ __forceinline__ void upk2(ull v, float& lo, float& hi) {
    asm("mov.b64 {%0, %1}, %2;" : "=f"(lo), "=f"(hi) : "l"(v));
}
__device__ __forceinline__ void ffma2(ull& d, ull a, ull b) {
    asm("fma.rn.f32x2 %0, %1, %2, %0;" : "+l"(d) : "l"(a), "l"(b));
}

// ---------------------------------------------------------------------------
// Init: zero h (both buffers), c, and outputs[:, 0, :]
// ---------------------------------------------------------------------------
__global__ void k_init(float* __restrict__ outp) {
    int i = blockIdx.x * blockDim.x + threadIdx.x;
    if (i < B * VOC) {
        int b = i / VOC, v = i % VOC;
        outp[(size_t)b * TT * VOC + v] = 0.0f;
    }
    if (i < B * DHID) { g_h[0][i] = 0.0f; g_h[1][i] = 0.0f; g_c[i] = 0.0f; }
}

// ---------------------------------------------------------------------------
// Transpose fc_W [VOC][KFC] -> g_fcwt [KFC][VOC] (once)
// ---------------------------------------------------------------------------
__global__ void k_transpose(const float* __restrict__ W) {
    __shared__ float tile[32][33];
    int tx = threadIdx.x, ty = threadIdx.y;          // 32 x 8
    int v0 = blockIdx.x * 32, k0 = blockIdx.y * 32;
    for (int r = ty; r < 32; r += 8) {
        int k = k0 + tx;
        tile[r][tx] = (k < KFC) ? W[(size_t)(v0 + r) * KFC + k] : 0.0f;
    }
    __syncthreads();
    for (int r = ty; r < 32; r += 8) {
        int k = k0 + r;
        if (k < KFC) g_fcwt[(size_t)k * VOC + v0 + tx] = tile[tx][r];
    }
}

// ---------------------------------------------------------------------------
// enc_proj[b,s,j] = attn_b[j] + sum_k enc[b,s,k] * attn_W[128+k][j]   (once)
// ---------------------------------------------------------------------------
__global__ void __launch_bounds__(128) k_encproj(const float* __restrict__ enc,
                                                 const float* __restrict__ attn_W,
                                                 const float* __restrict__ attn_b) {
    __shared__ __align__(16) float es[32 * 8];
    int j = threadIdx.x;
    int row0 = blockIdx.x * 32;
    float acc[32];
    float bj = attn_b[j];
#pragma unroll
    for (int r = 0; r < 32; r++) acc[r] = bj;
    const float* Wenc = attn_W + DHID * DHID;

    for (int k0 = 0; k0 < EHID; k0 += 8) {
        __syncthreads();
        int i0 = j;
        es[i0] = enc[(size_t)(row0 + (i0 >> 3)) * EHID + k0 + (i0 & 7)];
        int i1 = j + 128;
        es[i1] = enc[(size_t)(row0 + (i1 >> 3)) * EHID + k0 + (i1 & 7)];
        __syncthreads();
        float w[8];
#pragma unroll
        for (int kk = 0; kk < 8; kk++) w[kk] = Wenc[(size_t)(k0 + kk) * DHID + j];
#pragma unroll
        for (int r = 0; r < 32; r++) {
            const float4* e4 = (const float4*)(es + r * 8);
            float4 e0 = e4[0], e1 = e4[1];
            acc[r] = fmaf(e0.x, w[0], acc[r]); acc[r] = fmaf(e0.y, w[1], acc[r]);
            acc[r] = fmaf(e0.z, w[2], acc[r]); acc[r] = fmaf(e0.w, w[3], acc[r]);
            acc[r] = fmaf(e1.x, w[4], acc[r]); acc[r] = fmaf(e1.y, w[5], acc[r]);
            acc[r] = fmaf(e1.z, w[6], acc[r]); acc[r] = fmaf(e1.w, w[7], acc[r]);
        }
    }
#pragma unroll
    for (int r = 0; r < 32; r++)
        g_enc_proj[(size_t)(row0 + r) * DHID + j] = acc[r];
}

// ---------------------------------------------------------------------------
// Per-step scores: hp-proj, tanh scores (coalesced), softmax, emb gather.
// grid = B, 512 threads (16 warps x 16 s each).
// ---------------------------------------------------------------------------
__global__ void __launch_bounds__(512) k_score(
    const int* __restrict__ trg, const float* __restrict__ embt,
    const float* __restrict__ attn_W, const float* __restrict__ attn_v, int t)
{
    int b = blockIdx.x, tid = threadIdx.x;
    __shared__ float sh_h[DHID], sh_hp[DHID], sh_v[DHID];
    __shared__ float sh_a[S], sh_red[S];

    const float* hold = g_h[t & 1];
    if (tid < DHID) { sh_h[tid] = hold[b * DHID + tid]; sh_v[tid] = attn_v[tid]; }
    __syncthreads();

    if (tid < DHID) {
        float acc = 0.0f;
#pragma unroll 8
        for (int k = 0; k < DHID; k++)
            acc = fmaf(sh_h[k], attn_W[k * DHID + tid], acc);
        sh_hp[tid] = acc;
    }
    __syncthreads();

    {
        int w = tid >> 5, lane = tid & 31;
        const float* epb = g_enc_proj + (size_t)b * S * DHID;
        float hp0 = sh_hp[lane],      hp1 = sh_hp[lane + 32];
        float hp2 = sh_hp[lane + 64], hp3 = sh_hp[lane + 96];
        float v0 = sh_v[lane],        v1 = sh_v[lane + 32];
        float v2 = sh_v[lane + 64],   v3 = sh_v[lane + 96];
#pragma unroll 4
        for (int i = 0; i < 16; i++) {
            int s = w * 16 + i;
            const float* ep = epb + (size_t)s * DHID;
            float acc = tanhfast(ep[lane]      + hp0) * v0
                      + tanhfast(ep[lane + 32] + hp1) * v1
                      + tanhfast(ep[lane + 64] + hp2) * v2
                      + tanhfast(ep[lane + 96] + hp3) * v3;
#pragma unroll
            for (int o = 16; o > 0; o >>= 1)
                acc += __shfl_xor_sync(0xFFFFFFFFu, acc, o);
            if (lane == 0) sh_a[s] = acc;
        }
    }
    __syncthreads();

    // softmax over S=256
    if (tid < S) sh_red[tid] = sh_a[tid];
    __syncthreads();
    for (int off = S / 2; off > 0; off >>= 1) {
        if (tid < off) sh_red[tid] = fmaxf(sh_red[tid], sh_red[tid + off]);
        __syncthreads();
    }
    float mx = sh_red[0];
    __syncthreads();
    if (tid < S) { float e = __expf(sh_a[tid] - mx); sh_a[tid] = e; sh_red[tid] = e; }
    __syncthreads();
    for (int off = S / 2; off > 0; off >>= 1) {
        if (tid < off) sh_red[tid] += sh_red[tid + off];
        __syncthreads();
    }
    if (tid < S)
        g_attw[b * S + tid] = sh_a[tid] * __fdividef(1.0f, sh_red[0]);

    int tok = trg[b * TT + t];
    if (tid < EMBD)
        g_xcatT[(DHID + EHID + tid) * B + b] = embt[(size_t)tok * EMBD + tid];
}

// ---------------------------------------------------------------------------
// Per-step context: weighted[b][d] = sum_s a[s]*enc[b,s,d].
// grid = (6, 32), 128 threads, coalesced, MLP=8.
// ---------------------------------------------------------------------------
__global__ void __launch_bounds__(128) k_ctx(const float* __restrict__ enc) {
    int d = blockIdx.x * 128 + threadIdx.x;
    int b = blockIdx.y;
    __shared__ float sa[S];
    sa[threadIdx.x]       = g_attw[b * S + threadIdx.x];
    sa[threadIdx.x + 128] = g_attw[b * S + threadIdx.x + 128];
    __syncthreads();

    const float* e = enc + (size_t)b * S * EHID + d;
    float a[8];
#pragma unroll
    for (int j = 0; j < 8; j++) a[j] = 0.0f;
#pragma unroll 4
    for (int s = 0; s < S; s += 8) {
#pragma unroll
        for (int j = 0; j < 8; j++)
            a[j] = fmaf(sa[s + j], e[(size_t)(s + j) * EHID], a[j]);
    }
    float r = ((a[0] + a[1]) + (a[2] + a[3])) + ((a[4] + a[5]) + (a[6] + a[7]));
    g_xcatT[(DHID + d) * B + b] = r;                      // FC x rows 128..895
}

// ---------------------------------------------------------------------------
// Per-step LSTM, 2-way k-split: grid = 128 blocks (1 col each), 256 threads.
// ---------------------------------------------------------------------------
__global__ void __launch_bounds__(256) k_lstm(
    const float* __restrict__ W_ih, const float* __restrict__ W_hh,
    const float* __restrict__ b_ih, const float* __restrict__ b_hh, int t)
{
    int col = blockIdx.x;
    int tid = threadIdx.x;
    int half = tid >> 7;
    int gate = (tid >> 5) & 3;
    int b = tid & 31;
    int g = gate * DHID + col;

    __shared__ float sh_hold[32 * 129];
    __shared__ float sg[8][32];

    const float* hold = g_h[t & 1];
    for (int i = tid; i < B * DHID; i += 256)
        sh_hold[(i >> 7) * 129 + (i & 127)] = hold[i];
    __syncthreads();

    const float* Wg = W_ih + (size_t)g * KLSTM;
    float a0 = 0.f, a1 = 0.f, a2 = 0.f, a3 = 0.f;
    if (half == 0) {
        a0 = b_ih[g] + b_hh[g];
        const float* xe = g_xcatT + 896 * B + b;      // emb: x cols 0..199
#pragma unroll 2
        for (int k = 0; k < 200; k += 4) {
            float4 w = *(const float4*)(Wg + k);
            a0 = fmaf(w.x, xe[(k + 0) * B], a0);
            a1 = fmaf(w.y, xe[(k + 1) * B], a1);
            a2 = fmaf(w.z, xe[(k + 2) * B], a2);
            a3 = fmaf(w.w, xe[(k + 3) * B], a3);
        }
        const float* xw = g_xcatT - 72 * B + b;       // weighted: x cols 200..483
#pragma unroll 2
        for (int k = 200; k < 484; k += 4) {
            float4 w = *(const float4*)(Wg + k);
            a0 = fmaf(w.x, xw[(k + 0) * B], a0);
            a1 = fmaf(w.y, xw[(k + 1) * B], a1);
            a2 = fmaf(w.z, xw[(k + 2) * B], a2);
            a3 = fmaf(w.w, xw[(k + 3) * B], a3);
        }
    } else {
        const float* xw = g_xcatT - 72 * B + b;       // weighted: x cols 484..967
#pragma unroll 2
        for (int k = 484; k < 968; k += 4) {
            float4 w = *(const float4*)(Wg + k);
            a0 = fmaf(w.x, xw[(k + 0) * B], a0);
            a1 = fmaf(w.y, xw[(k + 1) * B], a1);
            a2 = fmaf(w.z, xw[(k + 2) * B], a2);
            a3 = fmaf(w.w, xw[(k + 3) * B], a3);
        }
        const float* Wh = W_hh + (size_t)g * DHID;
        const float* hb = sh_hold + b * 129;
#pragma unroll 4
        for (int k = 0; k < DHID; k += 4) {
            float4 w = *(const float4*)(Wh + k);
            a0 = fmaf(w.x, hb[k + 0], a0);
            a1 = fmaf(w.y, hb[k + 1], a1);
            a2 = fmaf(w.z, hb[k + 2], a2);
            a3 = fmaf(w.w, hb[k + 3], a3);
        }
    }
    sg[half * 4 + gate][b] = (a0 + a1) + (a2 + a3);
    __syncthreads();

    if (tid < 32) {
        float gi = sg[0][b] + sg[4][b];
        float gf = sg[1][b] + sg[5][b];
        float gg = sg[2][b] + sg[6][b];
        float go = sg[3][b] + sg[7][b];
        float c = g_c[b * DHID + col];
        c = sigfast(gf) * c + sigfast(gi) * tanhfast(gg);
        float h = sigfast(go) * tanhfast(c);
        g_c[b * DHID + col] = c;
        g_h[(t + 1) & 1][b * DHID + col] = h;
        g_xcatT[col * B + b] = h;                     // FC x rows 0..127
    }
}

// ---------------------------------------------------------------------------
// Per-step FC: cp.async pipeline + packed fp32x2 FFMA.
// grid = 125 blocks (SINGLE WAVE) x 256 thr. Block: 256 v x 32 b.
// Thread: 8 v (4 natural f32x2 pairs from smem) x 4 b (dup'd, ALU pipe).
// Per k/thread: 2 LDS.128 + 1 LDG.128 + 8 MOV + 16 FFMA2 (32 MACs).
// FMA-pipe floor ~37us/step; smem reads are 8-lane broadcast (non-binding).
// ---------------------------------------------------------------------------
#define FC_KC 8
#define FC_NST 4
#define FC_NSTG (KFC / FC_KC)   // 137

__global__ void __launch_bounds__(256) k_fc(const float* __restrict__ fc_b,
                                            float* __restrict__ outp, int t) {
    __shared__ __align__(16) float sw[FC_NST][FC_KC * 256];   // 32KB
    int tid = threadIdx.x;
    int v0 = blockIdx.x * 256;

    // loader: thread covers rows (tid>>6) and (tid>>6)+4, 16B column (tid&63)
    int lr0 = tid >> 6;                 // 0..3
    int lc  = (tid & 63) * 4;           // float offset in row
    const float* gsrc0 = g_fcwt + (size_t)lr0 * VOC + v0 + lc;
    const float* gsrc1 = g_fcwt + (size_t)(lr0 + 4) * VOC + v0 + lc;
    const size_t gstep = (size_t)FC_KC * VOC;
    uint32_t sd0 = (uint32_t)__cvta_generic_to_shared(&sw[0][lr0 * 256 + lc]);
    uint32_t sd1 = (uint32_t)__cvta_generic_to_shared(&sw[0][(lr0 + 4) * 256 + lc]);
    const uint32_t sstage = FC_KC * 256 * 4;                  // 8KB

#pragma unroll
    for (int s = 0; s < FC_NST - 1; s++) {
        cpasync16(sd0 + s * sstage, gsrc0 + (size_t)s * gstep);
        cpasync16(sd1 + s * sstage, gsrc1 + (size_t)s * gstep);
        cpcommit();
    }

    // compute mapping: 8-lane broadcast on w reads
    int vb   = (tid >> 5) * 4 + (tid & 3);   // 0..31 -> v = v0 + vb*8 .. +7
    int bgrp = (tid >> 2) & 7;               // 0..7  -> b = bgrp*4 .. +3

    ull acc[4][4];                            // [v-pair][b]
#pragma unroll
    for (int i = 0; i < 4; i++)
#pragma unroll
        for (int j = 0; j < 4; j++) acc[i][j] = 0ull;

    const float4* x4 = (const float4*)g_xcatT;   // x[k][bgrp*4..+3] = x4[k*8+bgrp]

    for (int stg = 0; stg < FC_NSTG; stg++) {
        cpwait<FC_NST - 2>();
        __syncthreads();
        const float* wbuf = sw[stg & (FC_NST - 1)] + vb * 8;
#pragma unroll
        for (int r = 0; r < FC_KC; r++) {
            const ulonglong2* wq = (const ulonglong2*)(wbuf + r * 256);
            ulonglong2 q0 = wq[0];               // v-pairs (0,1): v+0..3
            ulonglong2 q1 = wq[1];               // v-pairs (2,3): v+4..7
            float4 x = __ldg(x4 + (size_t)(stg * FC_KC + r) * 8 + bgrp);
            ull xd0 = pk2(x.x, x.x), xd1 = pk2(x.y, x.y);
            ull xd2 = pk2(x.z, x.z), xd3 = pk2(x.w, x.w);
            ffma2(acc[0][0], q0.x, xd0); ffma2(acc[0][1], q0.x, xd1);
            ffma2(acc[0][2], q0.x, xd2); ffma2(acc[0][3], q0.x, xd3);
            ffma2(acc[1][0], q0.y, xd0); ffma2(acc[1][1], q0.y, xd1);
            ffma2(acc[1][2], q0.y, xd2); ffma2(acc[1][3], q0.y, xd3);
            ffma2(acc[2][0], q1.x, xd0); ffma2(acc[2][1], q1.x, xd1);
            ffma2(acc[2][2], q1.x, xd2); ffma2(acc[2][3], q1.x, xd3);
            ffma2(acc[3][0], q1.y, xd0); ffma2(acc[3][1], q1.y, xd1);
            ffma2(acc[3][2], q1.y, xd2); ffma2(acc[3][3], q1.y, xd3);
        }
        int ns = stg + FC_NST - 1;
        if (ns < FC_NSTG) {
            uint32_t so = (ns & (FC_NST - 1)) * sstage;
            cpasync16(sd0 + so, gsrc0 + (size_t)ns * gstep);
            cpasync16(sd1 + so, gsrc1 + (size_t)ns * gstep);
        }
        cpcommit();
    }

    // epilogue: v = v0 + vb*8 + {0..7}, b = bgrp*4 + {0..3}
    int v = v0 + vb * 8;
    float4 bias0 = *(const float4*)(fc_b + v);
    float4 bias1 = *(const float4*)(fc_b + v + 4);
    const size_t bs = (size_t)TT * VOC;
    float* ob = outp + (size_t)(t + 1) * VOC + v;
#pragma unroll
    for (int j = 0; j < 4; j++) {
        int b = bgrp * 4 + j;
        float f0l, f0h, f1l, f1h, f2l, f2h, f3l, f3h;
        upk2(acc[0][j], f0l, f0h);
        upk2(acc[1][j], f1l, f1h);
        upk2(acc[2][j], f2l, f2h);
        upk2(acc[3][j], f3l, f3h);
        float4 oA = make_float4(f0l + bias0.x, f0h + bias0.y,
                                f1l + bias0.z, f1h + bias0.w);
        float4 oB = make_float4(f2l + bias1.x, f2h + bias1.y,
                                f3l + bias1.z, f3h + bias1.w);
        *(float4*)(ob + (size_t)b * bs)     = oA;
        *(float4*)(ob + (size_t)b * bs + 4) = oB;
    }
}

// ---------------------------------------------------------------------------
// Epilogue: argmax over V per (b,t) row
// ---------------------------------------------------------------------------
__global__ void __launch_bounds__(256) k_argmax(const float* __restrict__ outp,
                                                float* __restrict__ tokout) {
    int row = blockIdx.x;
    const float* p = outp + (size_t)row * VOC;
    int tid = threadIdx.x;
    float best = -1e30f;
    int bi = VOC;
    for (int i = tid; i < VOC; i += 256) {
        float vv = p[i];
        if (vv > best || (vv == best && i < bi)) { best = vv; bi = i; }
    }
    __shared__ float sv[256];
    __shared__ int si[256];
    sv[tid] = best; si[tid] = bi;
    __syncthreads();
    for (int off = 128; off > 0; off >>= 1) {
        if (tid < off) {
            float ov = sv[tid + off]; int oi = si[tid + off];
            if (ov > sv[tid] || (ov == sv[tid] && oi < si[tid])) { sv[tid] = ov; si[tid] = oi; }
        }
        __syncthreads();
    }
    if (tid == 0) tokout[row] = (float)si[0];
}

// ---------------------------------------------------------------------------
extern "C" void kernel_launch(void* const* d_in, const int* in_sizes, int n_in,
                              void* d_out, int out_size) {
    const float* enc    = (const float*)d_in[0];
    const int*   trg    = (const int*)d_in[1];
    const float* embt   = (const float*)d_in[2];
    const float* attn_W = (const float*)d_in[3];
    const float* attn_b = (const float*)d_in[4];
    const float* attn_v = (const float*)d_in[5];
    const float* W_ih   = (const float*)d_in[6];
    const float* W_hh   = (const float*)d_in[7];
    const float* b_ih   = (const float*)d_in[8];
    const float* b_hh   = (const float*)d_in[9];
    const float* fc_W   = (const float*)d_in[10];
    const float* fc_b   = (const float*)d_in[11];
    float* outp = (float*)d_out;
    (void)in_sizes; (void)n_in;

    k_init<<<(B * VOC + 255) / 256, 256>>>(outp);
    k_transpose<<<dim3(VOC / 32, (KFC + 31) / 32), dim3(32, 8)>>>(fc_W);
    k_encproj<<<(B * S) / 32, 128>>>(enc, attn_W, attn_b);

    for (int t = 0; t < NSTEP; t++) {
        k_score<<<B, 512>>>(trg, embt, attn_W, attn_v, t);
        k_ctx<<<dim3(EHID / 128, B), 128>>>(enc);
        k_lstm<<<DHID, 256>>>(W_ih, W_hh, b_ih, b_hh, t);
        k_fc<<<VOC / 256, 256>>>(fc_b, outp, t);
    }

    long long need = (long long)B * TT * VOC + (long long)B * TT;
    if ((long long)out_size >= need) {
        k_argmax<<<B * TT, 256>>>(outp, outp + (size_t)B * TT * VOC);
    }
}

// round 9
// speedup vs baseline: 1.8958x; 1.8958x over previous
#include <cuda_runtime.h>
#include <cuda_bf16.h>
#include <math.h>
#include <stdint.h>

// Problem dims
#define B 32
#define S 256
#define EHID 768
#define DHID 128
#define EMBD 200
#define VOC 32000
#define TT 96
#define NSTEP 95
#define KFC 1096    // DHID + EHID + EMBD
#define KLSTM 968   // EMBD + EHID
#define NCH 69      // ceil(KFC/16) k-chunks of 16
#define NTILES 4000 // VOC/8 n-tiles of 8

// Scratch (static device globals: allowed; no runtime allocation)
__device__ uint4  g_wfrag[(size_t)NCH * NTILES * 32]; // bf16 hi/lo B-fragments, ~141MB
__device__ uint4  g_xfragA[NCH * 2 * 2 * 32];         // [c][mt][hi/lo][lane] A-fragments
__device__ float  g_enc_proj[B * S * DHID];           // step-invariant attention term
__device__ float  g_xcatT[KFC * B];                   // FC input, transposed [k][b]
__device__ float  g_xhist[NSTEP * KFC * B];           // xcat history for exact argmax, 13MB
__device__ float  g_attw[B * S];                      // softmax attention weights
__device__ float  g_h[2][B * DHID];                   // ping-pong across steps
__device__ float  g_c[B * DHID];

// fast activations (validated: rel_err stays ~7e-7 on fp32 path)
__device__ __forceinline__ float sigfast(float x) {
    return __fdividef(1.0f, 1.0f + __expf(-x));
}
__device__ __forceinline__ float tanhfast(float x) {
    x = fminf(fmaxf(x, -15.0f), 15.0f);
    float e = __expf(2.0f * x);
    return __fdividef(e - 1.0f, e + 1.0f);
}

// cp.async helpers
__device__ __forceinline__ void cpasync16(uint32_t dst, const void* src) {
    asm volatile("cp.async.cg.shared.global [%0], [%1], 16;" :: "r"(dst), "l"(src));
}
__device__ __forceinline__ void cpcommit() {
    asm volatile("cp.async.commit_group;" ::: "memory");
}
template <int N> __device__ __forceinline__ void cpwait() {
    asm volatile("cp.async.wait_group %0;" :: "n"(N) : "memory");
}

// bf16 pair pack: element a in low 16 bits, b in high 16 bits
__device__ __forceinline__ uint32_t pkbf(__nv_bfloat16 a, __nv_bfloat16 b) {
    uint32_t lo = (uint32_t)__bfloat16_as_ushort(a);
    uint32_t hi = (uint32_t)__bfloat16_as_ushort(b);
    return lo | (hi << 16);
}
__device__ __forceinline__ void split2(float v, __nv_bfloat16& h, __nv_bfloat16& l) {
    h = __float2bfloat16_rn(v);
    l = __float2bfloat16_rn(v - __bfloat162float(h));
}

// warp-level bf16 tensor-core mma, m16n8k16, fp32 accumulate
__device__ __forceinline__ void mma16816(float* d, uint32_t a0, uint32_t a1,
                                         uint32_t a2, uint32_t a3,
                                         uint32_t b0, uint32_t b1) {
    asm volatile(
        "mma.sync.aligned.m16n8k16.row.col.f32.bf16.bf16.f32 "
        "{%0,%1,%2,%3}, {%4,%5,%6,%7}, {%8,%9}, {%0,%1,%2,%3};"
        : "+f"(d[0]), "+f"(d[1]), "+f"(d[2]), "+f"(d[3])
        : "r"(a0), "r"(a1), "r"(a2), "r"(a3), "r"(b0), "r"(b1));
}

// ---------------------------------------------------------------------------
// Init: zero h (both buffers), c, and outputs[:, 0, :]
// ---------------------------------------------------------------------------
__global__ void k_init(float* __restrict__ outp) {
    int i = blockIdx.x * blockDim.x + threadIdx.x;
    if (i < B * VOC) {
        int b = i / VOC, v = i % VOC;
        outp[(size_t)b * TT * VOC + v] = 0.0f;
    }
    if (i < B * DHID) { g_h[0][i] = 0.0f; g_h[1][i] = 0.0f; g_c[i] = 0.0f; }
}

// ---------------------------------------------------------------------------
// Repack fc_W [VOC][KFC] into bf16 hi/lo B-fragments (fragment-ordered).
// grid = (500 ngroups, 69 chunks), 256 threads. Block: 64 n x 16 k.
// Out lane content (per chunk c, ntile nt, lane l; g=l/4, t=l%4):
//   .x = {wh[k0+2t][n], wh[k0+2t+1][n]}   .y = {wh[k0+2t+8][n], wh[k0+2t+9][n]}
//   .z/.w = same for wl.   n = nt*8 + g, k0 = c*16.
// ---------------------------------------------------------------------------
__global__ void __launch_bounds__(256) k_wprep(const float* __restrict__ W) {
    __shared__ float ws[64][17];
    int c = blockIdx.y, ng = blockIdx.x;
    int k0 = c * 16, n0g = ng * 64;
    int tid = threadIdx.x;

    for (int idx = tid; idx < 64 * 16; idx += 256) {
        int r = idx >> 4, q = idx & 15;
        int kg = k0 + q;
        ws[r][q] = (kg < KFC) ? W[(size_t)(n0g + r) * KFC + kg] : 0.0f;
    }
    __syncthreads();

    int ntl = tid >> 5;           // 0..7
    int l = tid & 31;
    int g = l >> 2, t4 = l & 3;
    int nr = ntl * 8 + g;
    float v0 = ws[nr][2 * t4], v1 = ws[nr][2 * t4 + 1];
    float v2 = ws[nr][2 * t4 + 8], v3 = ws[nr][2 * t4 + 9];
    __nv_bfloat16 h0, l0, h1, l1, h2, l2, h3, l3;
    split2(v0, h0, l0); split2(v1, h1, l1);
    split2(v2, h2, l2); split2(v3, h3, l3);
    uint4 o;
    o.x = pkbf(h0, h1); o.y = pkbf(h2, h3);
    o.z = pkbf(l0, l1); o.w = pkbf(l2, l3);
    int nt = ng * 8 + ntl;
    g_wfrag[((size_t)c * NTILES + nt) * 32 + l] = o;
}

// ---------------------------------------------------------------------------
// enc_proj[b,s,j] = attn_b[j] + sum_k enc[b,s,k] * attn_W[128+k][j]   (once)
// ---------------------------------------------------------------------------
__global__ void __launch_bounds__(128) k_encproj(const float* __restrict__ enc,
                                                 const float* __restrict__ attn_W,
                                                 const float* __restrict__ attn_b) {
    __shared__ __align__(16) float es[32 * 8];
    int j = threadIdx.x;
    int row0 = blockIdx.x * 32;
    float acc[32];
    float bj = attn_b[j];
#pragma unroll
    for (int r = 0; r < 32; r++) acc[r] = bj;
    const float* Wenc = attn_W + DHID * DHID;

    for (int k0 = 0; k0 < EHID; k0 += 8) {
        __syncthreads();
        int i0 = j;
        es[i0] = enc[(size_t)(row0 + (i0 >> 3)) * EHID + k0 + (i0 & 7)];
        int i1 = j + 128;
        es[i1] = enc[(size_t)(row0 + (i1 >> 3)) * EHID + k0 + (i1 & 7)];
        __syncthreads();
        float w[8];
#pragma unroll
        for (int kk = 0; kk < 8; kk++) w[kk] = Wenc[(size_t)(k0 + kk) * DHID + j];
#pragma unroll
        for (int r = 0; r < 32; r++) {
            const float4* e4 = (const float4*)(es + r * 8);
            float4 e0 = e4[0], e1 = e4[1];
            acc[r] = fmaf(e0.x, w[0], acc[r]); acc[r] = fmaf(e0.y, w[1], acc[r]);
            acc[r] = fmaf(e0.z, w[2], acc[r]); acc[r] = fmaf(e0.w, w[3], acc[r]);
            acc[r] = fmaf(e1.x, w[4], acc[r]); acc[r] = fmaf(e1.y, w[5], acc[r]);
            acc[r] = fmaf(e1.z, w[6], acc[r]); acc[r] = fmaf(e1.w, w[7], acc[r]);
        }
    }
#pragma unroll
    for (int r = 0; r < 32; r++)
        g_enc_proj[(size_t)(row0 + r) * DHID + j] = acc[r];
}

// ---------------------------------------------------------------------------
// Per-step scores: hp-proj, tanh scores (coalesced), softmax, emb gather.
// grid = B, 512 threads (16 warps x 16 s each).
// ---------------------------------------------------------------------------
__global__ void __launch_bounds__(512) k_score(
    const int* __restrict__ trg, const float* __restrict__ embt,
    const float* __restrict__ attn_W, const float* __restrict__ attn_v, int t)
{
    int b = blockIdx.x, tid = threadIdx.x;
    __shared__ float sh_h[DHID], sh_hp[DHID], sh_v[DHID];
    __shared__ float sh_a[S], sh_red[S];

    const float* hold = g_h[t & 1];
    if (tid < DHID) { sh_h[tid] = hold[b * DHID + tid]; sh_v[tid] = attn_v[tid]; }
    __syncthreads();

    if (tid < DHID) {
        float acc = 0.0f;
#pragma unroll 8
        for (int k = 0; k < DHID; k++)
            acc = fmaf(sh_h[k], attn_W[k * DHID + tid], acc);
        sh_hp[tid] = acc;
    }
    __syncthreads();

    {
        int w = tid >> 5, lane = tid & 31;
        const float* epb = g_enc_proj + (size_t)b * S * DHID;
        float hp0 = sh_hp[lane],      hp1 = sh_hp[lane + 32];
        float hp2 = sh_hp[lane + 64], hp3 = sh_hp[lane + 96];
        float v0 = sh_v[lane],        v1 = sh_v[lane + 32];
        float v2 = sh_v[lane + 64],   v3 = sh_v[lane + 96];
#pragma unroll 8
        for (int i = 0; i < 16; i++) {
            int s = w * 16 + i;
            const float* ep = epb + (size_t)s * DHID;
            float acc = tanhfast(ep[lane]      + hp0) * v0
                      + tanhfast(ep[lane + 32] + hp1) * v1
                      + tanhfast(ep[lane + 64] + hp2) * v2
                      + tanhfast(ep[lane + 96] + hp3) * v3;
#pragma unroll
            for (int o = 16; o > 0; o >>= 1)
                acc += __shfl_xor_sync(0xFFFFFFFFu, acc, o);
            if (lane == 0) sh_a[s] = acc;
        }
    }
    __syncthreads();

    // softmax over S=256
    if (tid < S) sh_red[tid] = sh_a[tid];
    __syncthreads();
    for (int off = S / 2; off > 0; off >>= 1) {
        if (tid < off) sh_red[tid] = fmaxf(sh_red[tid], sh_red[tid + off]);
        __syncthreads();
    }
    float mx = sh_red[0];
    __syncthreads();
    if (tid < S) { float e = __expf(sh_a[tid] - mx); sh_a[tid] = e; sh_red[tid] = e; }
    __syncthreads();
    for (int off = S / 2; off > 0; off >>= 1) {
        if (tid < off) sh_red[tid] += sh_red[tid + off];
        __syncthreads();
    }
    if (tid < S)
        g_attw[b * S + tid] = sh_a[tid] * __fdividef(1.0f, sh_red[0]);

    int tok = trg[b * TT + t];
    if (tid < EMBD)
        g_xcatT[(DHID + EHID + tid) * B + b] = embt[(size_t)tok * EMBD + tid];
}

// ---------------------------------------------------------------------------
// Per-step context: weighted[b][d] = sum_s a[s]*enc[b,s,d]. grid (6,32).
// ---------------------------------------------------------------------------
__global__ void __launch_bounds__(128) k_ctx(const float* __restrict__ enc) {
    int d = blockIdx.x * 128 + threadIdx.x;
    int b = blockIdx.y;
    __shared__ float sa[S];
    sa[threadIdx.x]       = g_attw[b * S + threadIdx.x];
    sa[threadIdx.x + 128] = g_attw[b * S + threadIdx.x + 128];
    __syncthreads();

    const float* e = enc + (size_t)b * S * EHID + d;
    float a[8];
#pragma unroll
    for (int j = 0; j < 8; j++) a[j] = 0.0f;
#pragma unroll 4
    for (int s = 0; s < S; s += 8) {
#pragma unroll
        for (int j = 0; j < 8; j++)
            a[j] = fmaf(sa[s + j], e[(size_t)(s + j) * EHID], a[j]);
    }
    float r = ((a[0] + a[1]) + (a[2] + a[3])) + ((a[4] + a[5]) + (a[6] + a[7]));
    g_xcatT[(DHID + d) * B + b] = r;                      // FC x rows 128..895
}

// ---------------------------------------------------------------------------
// Per-step LSTM, 2-way k-split: grid = 128 blocks (1 col each), 256 threads.
// ---------------------------------------------------------------------------
__global__ void __launch_bounds__(256) k_lstm(
    const float* __restrict__ W_ih, const float* __restrict__ W_hh,
    const float* __restrict__ b_ih, const float* __restrict__ b_hh, int t)
{
    int col = blockIdx.x;
    int tid = threadIdx.x;
    int half = tid >> 7;
    int gate = (tid >> 5) & 3;
    int b = tid & 31;
    int g = gate * DHID + col;

    __shared__ float sh_hold[32 * 129];
    __shared__ float sg[8][32];

    const float* hold = g_h[t & 1];
    for (int i = tid; i < B * DHID; i += 256)
        sh_hold[(i >> 7) * 129 + (i & 127)] = hold[i];
    __syncthreads();

    const float* Wg = W_ih + (size_t)g * KLSTM;
    float a0 = 0.f, a1 = 0.f, a2 = 0.f, a3 = 0.f;
    if (half == 0) {
        a0 = b_ih[g] + b_hh[g];
        const float* xe = g_xcatT + 896 * B + b;      // emb: x cols 0..199
#pragma unroll 2
        for (int k = 0; k < 200; k += 4) {
            float4 w = *(const float4*)(Wg + k);
            a0 = fmaf(w.x, xe[(k + 0) * B], a0);
            a1 = fmaf(w.y, xe[(k + 1) * B], a1);
            a2 = fmaf(w.z, xe[(k + 2) * B], a2);
            a3 = fmaf(w.w, xe[(k + 3) * B], a3);
        }
        const float* xw = g_xcatT - 72 * B + b;       // weighted: x cols 200..483
#pragma unroll 2
        for (int k = 200; k < 484; k += 4) {
            float4 w = *(const float4*)(Wg + k);
            a0 = fmaf(w.x, xw[(k + 0) * B], a0);
            a1 = fmaf(w.y, xw[(k + 1) * B], a1);
            a2 = fmaf(w.z, xw[(k + 2) * B], a2);
            a3 = fmaf(w.w, xw[(k + 3) * B], a3);
        }
    } else {
        const float* xw = g_xcatT - 72 * B + b;       // weighted: x cols 484..967
#pragma unroll 2
        for (int k = 484; k < 968; k += 4) {
            float4 w = *(const float4*)(Wg + k);
            a0 = fmaf(w.x, xw[(k + 0) * B], a0);
            a1 = fmaf(w.y, xw[(k + 1) * B], a1);
            a2 = fmaf(w.z, xw[(k + 2) * B], a2);
            a3 = fmaf(w.w, xw[(k + 3) * B], a3);
        }
        const float* Wh = W_hh + (size_t)g * DHID;
        const float* hb = sh_hold + b * 129;
#pragma unroll 4
        for (int k = 0; k < DHID; k += 4) {
            float4 w = *(const float4*)(Wh + k);
            a0 = fmaf(w.x, hb[k + 0], a0);
            a1 = fmaf(w.y, hb[k + 1], a1);
            a2 = fmaf(w.z, hb[k + 2], a2);
            a3 = fmaf(w.w, hb[k + 3], a3);
        }
    }
    sg[half * 4 + gate][b] = (a0 + a1) + (a2 + a3);
    __syncthreads();

    if (tid < 32) {
        float gi = sg[0][b] + sg[4][b];
        float gf = sg[1][b] + sg[5][b];
        float gg = sg[2][b] + sg[6][b];
        float go = sg[3][b] + sg[7][b];
        float c = g_c[b * DHID + col];
        c = sigfast(gf) * c + sigfast(gi) * tanhfast(gg);
        float h = sigfast(go) * tanhfast(c);
        g_c[b * DHID + col] = c;
        g_h[(t + 1) & 1][b * DHID + col] = h;
        g_xcatT[col * B + b] = h;                     // FC x rows 0..127
    }
}

// ---------------------------------------------------------------------------
// Per-step x prep: build bf16 hi/lo A-fragments + save fp32 xcat history.
// grid = 69 (chunks), 128 threads.
// ---------------------------------------------------------------------------
__global__ void __launch_bounds__(128) k_xprep(int t) {
    __shared__ float xs[16][33];
    int c = blockIdx.x, tid = threadIdx.x;
    int k0 = c * 16;

    for (int idx = tid; idx < 512; idx += 128) {
        int kl = idx >> 5, bb = idx & 31;
        int kg = k0 + kl;
        xs[kl][bb] = (kg < KFC) ? g_xcatT[kg * B + bb] : 0.0f;
    }
    __syncthreads();

    int mt = tid >> 6;            // 0,1
    int l = (tid >> 1) & 31;
    int part = tid & 1;           // 0=hi, 1=lo
    int g = l >> 2, t4 = l & 3;
    int b0 = mt * 16 + g;

    // A row-major m16k16: a0:{A[g][2t],A[g][2t+1]} a1:{A[g+8][..]} a2/a3: k+8
    float v00 = xs[2 * t4][b0],     v01 = xs[2 * t4 + 1][b0];
    float v10 = xs[2 * t4][b0 + 8], v11 = xs[2 * t4 + 1][b0 + 8];
    float v20 = xs[2 * t4 + 8][b0],     v21 = xs[2 * t4 + 9][b0];
    float v30 = xs[2 * t4 + 8][b0 + 8], v31 = xs[2 * t4 + 9][b0 + 8];

    __nv_bfloat16 h, lo;
    uint4 o;
    if (part == 0) {
        split2(v00, h, lo); uint32_t p00 = pkbf(h, h) & 0xFFFF; (void)p00;
        // build hi parts
        __nv_bfloat16 h00, l00, h01, l01, h10, l10, h11, l11;
        __nv_bfloat16 h20, l20, h21, l21, h30, l30, h31, l31;
        split2(v00, h00, l00); split2(v01, h01, l01);
        split2(v10, h10, l10); split2(v11, h11, l11);
        split2(v20, h20, l20); split2(v21, h21, l21);
        split2(v30, h30, l30); split2(v31, h31, l31);
        o.x = pkbf(h00, h01); o.y = pkbf(h10, h11);
        o.z = pkbf(h20, h21); o.w = pkbf(h30, h31);
    } else {
        __nv_bfloat16 h00, l00, h01, l01, h10, l10, h11, l11;
        __nv_bfloat16 h20, l20, h21, l21, h30, l30, h31, l31;
        split2(v00, h00, l00); split2(v01, h01, l01);
        split2(v10, h10, l10); split2(v11, h11, l11);
        split2(v20, h20, l20); split2(v21, h21, l21);
        split2(v30, h30, l30); split2(v31, h31, l31);
        o.x = pkbf(l00, l01); o.y = pkbf(l10, l11);
        o.z = pkbf(l20, l21); o.w = pkbf(l30, l31);
    }
    g_xfragA[((c * 2 + mt) * 2 + part) * 32 + l] = o;

    // save fp32 xcat slice for exact argmax epilogue
    for (int idx = tid; idx < 512; idx += 128) {
        int i = c * 512 + idx;
        if (i < KFC * B) g_xhist[(size_t)t * (KFC * B) + i] = g_xcatT[i];
    }
}

// ---------------------------------------------------------------------------
// Per-step FC on tensor cores (mma.sync bf16, 3-term split precision).
// grid = 125 blocks (single wave) x 256 thr. Block: 32 b x 256 n.
// Per warp: 4 ntiles. cp.async 3-stage pipeline of fragment-ordered weights.
// ---------------------------------------------------------------------------
#define FC_NST 3

__global__ void __launch_bounds__(256) k_fc(const float* __restrict__ fc_b,
                                            float* __restrict__ outp, int t) {
    __shared__ uint4 swq[FC_NST][1024];         // 3 x 16KB = 48KB
    int tid = threadIdx.x;
    int lane = tid & 31, wrp = tid >> 5;
    int n0 = blockIdx.x * 256;
    int nt0 = blockIdx.x * 32;

    const uint4* gsrc = g_wfrag + (size_t)nt0 * 32;
    const size_t gstep = (size_t)NTILES * 32;   // uint4 per chunk
    uint32_t sbase = (uint32_t)__cvta_generic_to_shared(&swq[0][0]);
    const uint32_t sstage = 1024 * 16;

    // prologue: stages 0,1
#pragma unroll
    for (int s = 0; s < FC_NST - 1; s++) {
#pragma unroll
        for (int j = 0; j < 4; j++) {
            int e = tid + j * 256;
            cpasync16(sbase + s * sstage + e * 16, gsrc + (size_t)s * gstep + e);
        }
        cpcommit();
    }

    float acc[2][4][4];
#pragma unroll
    for (int m = 0; m < 2; m++)
#pragma unroll
        for (int i = 0; i < 4; i++)
#pragma unroll
            for (int j = 0; j < 4; j++) acc[m][i][j] = 0.0f;

    for (int c = 0; c < NCH; c++) {
        cpwait<FC_NST - 2>();
        __syncthreads();

        // A fragments (broadcast across warps; L1-resident)
        uint4 ah0 = __ldg(&g_xfragA[((c * 2 + 0) * 2 + 0) * 32 + lane]);
        uint4 ah1 = __ldg(&g_xfragA[((c * 2 + 1) * 2 + 0) * 32 + lane]);
        uint4 al0 = __ldg(&g_xfragA[((c * 2 + 0) * 2 + 1) * 32 + lane]);
        uint4 al1 = __ldg(&g_xfragA[((c * 2 + 1) * 2 + 1) * 32 + lane]);

        const uint4* wbuf = swq[c % FC_NST] + wrp * 4 * 32;
#pragma unroll
        for (int i = 0; i < 4; i++) {
            uint4 bq = wbuf[i * 32 + lane];     // {b0h,b1h,b0l,b1l}
            // term xh @ wh
            mma16816(acc[0][i], ah0.x, ah0.y, ah0.z, ah0.w, bq.x, bq.y);
            mma16816(acc[1][i], ah1.x, ah1.y, ah1.z, ah1.w, bq.x, bq.y);
            // term xl @ wh
            mma16816(acc[0][i], al0.x, al0.y, al0.z, al0.w, bq.x, bq.y);
            mma16816(acc[1][i], al1.x, al1.y, al1.z, al1.w, bq.x, bq.y);
            // term xh @ wl
            mma16816(acc[0][i], ah0.x, ah0.y, ah0.z, ah0.w, bq.z, bq.w);
            mma16816(acc[1][i], ah1.x, ah1.y, ah1.z, ah1.w, bq.z, bq.w);
        }

        int ns = c + FC_NST - 1;
        if (ns < NCH) {
#pragma unroll
            for (int j = 0; j < 4; j++) {
                int e = tid + j * 256;
                cpasync16(sbase + (ns % FC_NST) * sstage + e * 16,
                          gsrc + (size_t)ns * gstep + e);
            }
        }
        cpcommit();
    }

    // epilogue: D frag c0:D[g][2t] c1:D[g][2t+1] c2:D[g+8][2t] c3:D[g+8][2t+1]
    int g = lane >> 2, t4 = lane & 3;
#pragma unroll
    for (int m = 0; m < 2; m++) {
#pragma unroll
        for (int i = 0; i < 4; i++) {
            int n = n0 + (wrp * 4 + i) * 8 + 2 * t4;
            float b0 = fc_b[n], b1 = fc_b[n + 1];
            int br = m * 16 + g;
            size_t o1 = ((size_t)br * TT + (t + 1)) * VOC + n;
            size_t o2 = ((size_t)(br + 8) * TT + (t + 1)) * VOC + n;
            outp[o1]     = acc[m][i][0] + b0;
            outp[o1 + 1] = acc[m][i][1] + b1;
            outp[o2]     = acc[m][i][2] + b0;
            outp[o2 + 1] = acc[m][i][3] + b1;
        }
    }
}

// ---------------------------------------------------------------------------
// Epilogue argmax: approx top-2 scan, then EXACT fp32 recompute of both
// candidate logits from saved xcat history; pick winner (first-index ties).
// ---------------------------------------------------------------------------
__global__ void __launch_bounds__(256) k_argmax(const float* __restrict__ outp,
                                                const float* __restrict__ fc_W,
                                                const float* __restrict__ fc_b,
                                                float* __restrict__ tokout) {
    int row = blockIdx.x;            // b*TT + tt
    int b = row / TT, tt = row % TT;
    int tid = threadIdx.x;
    if (tt == 0) { if (tid == 0) tokout[row] = 0.0f; return; }

    const float* p = outp + ((size_t)b * TT + tt) * VOC;
    __shared__ float sv[256];
    __shared__ int si[256];
    __shared__ float dre[2];

    // pass 1: global max (first index on ties)
    float best = -1e30f; int bi = 0;
    for (int i = tid; i < VOC; i += 256) {
        float v = p[i];
        if (v > best) { best = v; bi = i; }
    }
    sv[tid] = best; si[tid] = bi;
    __syncthreads();
    for (int off = 128; off > 0; off >>= 1) {
        if (tid < off) {
            if (sv[tid + off] > sv[tid] ||
                (sv[tid + off] == sv[tid] && si[tid + off] < si[tid])) {
                sv[tid] = sv[tid + off]; si[tid] = si[tid + off];
            }
        }
        __syncthreads();
    }
    int i1 = si[0];
    __syncthreads();

    // pass 2: runner-up (exclude i1)
    best = -1e30f; bi = 0;
    for (int i = tid; i < VOC; i += 256) {
        if (i == i1) continue;
        float v = p[i];
        if (v > best) { best = v; bi = i; }
    }
    sv[tid] = best; si[tid] = bi;
    __syncthreads();
    for (int off = 128; off > 0; off >>= 1) {
        if (tid < off) {
            if (sv[tid + off] > sv[tid] ||
                (sv[tid + off] == sv[tid] && si[tid + off] < si[tid])) {
                sv[tid] = sv[tid + off]; si[tid] = si[tid + off];
            }
        }
        __syncthreads();
    }
    int i2 = si[0];
    __syncthreads();

    // exact fp32 recompute of the two candidates
    int wrp = tid >> 5, lane = tid & 31;
    if (wrp < 2) {
        int idx = (wrp == 0) ? i1 : i2;
        const float* wr = fc_W + (size_t)idx * KFC;
        const float* xr = g_xhist + (size_t)(tt - 1) * (KFC * B);
        float a = 0.0f;
        for (int k = lane; k < KFC; k += 32)
            a = fmaf(xr[k * B + b], wr[k], a);
#pragma unroll
        for (int o = 16; o > 0; o >>= 1)
            a += __shfl_xor_sync(0xFFFFFFFFu, a, o);
        if (lane == 0) dre[wrp] = a + fc_b[idx];
    }
    __syncthreads();
    if (tid == 0) {
        float d1 = dre[0], d2 = dre[1];
        int winner = i1;
        if (d2 > d1 || (d2 == d1 && i2 < i1)) winner = i2;
        tokout[row] = (float)winner;
    }
}

// ---------------------------------------------------------------------------
extern "C" void kernel_launch(void* const* d_in, const int* in_sizes, int n_in,
                              void* d_out, int out_size) {
    const float* enc    = (const float*)d_in[0];
    const int*   trg    = (const int*)d_in[1];
    const float* embt   = (const float*)d_in[2];
    const float* attn_W = (const float*)d_in[3];
    const float* attn_b = (const float*)d_in[4];
    const float* attn_v = (const float*)d_in[5];
    const float* W_ih   = (const float*)d_in[6];
    const float* W_hh   = (const float*)d_in[7];
    const float* b_ih   = (const float*)d_in[8];
    const float* b_hh   = (const float*)d_in[9];
    const float* fc_W   = (const float*)d_in[10];
    const float* fc_b   = (const float*)d_in[11];
    float* outp = (float*)d_out;
    (void)in_sizes; (void)n_in;

    k_init<<<(B * VOC + 255) / 256, 256>>>(outp);
    k_wprep<<<dim3(NTILES / 8, NCH), 256>>>(fc_W);
    k_encproj<<<(B * S) / 32, 128>>>(enc, attn_W, attn_b);

    for (int t = 0; t < NSTEP; t++) {
        k_score<<<B, 512>>>(trg, embt, attn_W, attn_v, t);
        k_ctx<<<dim3(EHID / 128, B), 128>>>(enc);
        k_lstm<<<DHID, 256>>>(W_ih, W_hh, b_ih, b_hh, t);
        k_xprep<<<NCH, 128>>>(t);
        k_fc<<<VOC / 256, 256>>>(fc_b, outp, t);
    }

    long long need = (long long)B * TT * VOC + (long long)B * TT;
    if ((long long)out_size >= need) {
        k_argmax<<<B * TT, 256>>>(outp, fc_W, fc_b,
                                  outp + (size_t)B * TT * VOC);
    }
}

// round 10
// speedup vs baseline: 1.9886x; 1.0489x over previous
#include <cuda_runtime.h>
#include <cuda_bf16.h>
#include <math.h>
#include <stdint.h>

// Problem dims
#define B 32
#define S 256
#define EHID 768
#define DHID 128
#define EMBD 200
#define VOC 32000
#define TT 96
#define NSTEP 95
#define KFC 1096    // DHID + EHID + EMBD
#define KLSTM 968   // EMBD + EHID
#define NCH 69      // ceil(KFC/16) k-chunks of 16
#define NTILES 4000 // VOC/8 n-tiles of 8

// Scratch (static device globals: allowed; no runtime allocation)
__device__ uint4  g_wfrag[(size_t)NCH * NTILES * 32]; // bf16 hi/lo B-fragments, ~141MB
__device__ uint4  g_xfragA[NCH * 2 * 2 * 32];         // [c][mt][hi/lo][lane] A-fragments
__device__ float  g_enc_proj[B * S * DHID];           // step-invariant attention term
__device__ float  g_xcatT[KFC * B];                   // FC input, transposed [k][b]
__device__ float  g_xhist[NSTEP * KFC * B];           // xcat history for exact argmax
__device__ float  g_scr[B * S];                       // raw attention scores
__device__ float  g_h[2][B * DHID];                   // ping-pong across steps
__device__ float  g_c[B * DHID];

// fast activations (validated across rounds)
__device__ __forceinline__ float sigfast(float x) {
    return __fdividef(1.0f, 1.0f + __expf(-x));
}
__device__ __forceinline__ float tanhfast(float x) {
    x = fminf(fmaxf(x, -15.0f), 15.0f);
    float e = __expf(2.0f * x);
    return __fdividef(e - 1.0f, e + 1.0f);
}

// mbarrier + bulk-copy helpers
__device__ __forceinline__ void mbar_init(uint32_t a, uint32_t cnt) {
    asm volatile("mbarrier.init.shared.b64 [%0], %1;" :: "r"(a), "r"(cnt) : "memory");
}
__device__ __forceinline__ void mbar_expect(uint32_t a, uint32_t bytes) {
    asm volatile("mbarrier.arrive.expect_tx.shared.b64 _, [%0], %1;"
                 :: "r"(a), "r"(bytes) : "memory");
}
__device__ __forceinline__ void mbar_wait(uint32_t a, uint32_t parity) {
    uint32_t done;
    asm volatile(
        "{\n\t.reg .pred p;\n\t"
        "mbarrier.try_wait.parity.acquire.cta.shared::cta.b64 p, [%1], %2;\n\t"
        "selp.b32 %0, 1, 0, p;\n\t}"
        : "=r"(done) : "r"(a), "r"(parity) : "memory");
    if (!done) {
        asm volatile(
            "{\n\t.reg .pred P1;\n\t"
            "W_%=:\n\t"
            "mbarrier.try_wait.parity.acquire.cta.shared::cta.b64 P1, [%0], %1, 0x989680;\n\t"
            "@P1 bra.uni D_%=;\n\t"
            "bra.uni W_%=;\n\t"
            "D_%=:\n\t}"
            :: "r"(a), "r"(parity) : "memory");
    }
}
// single-instruction 16KB bulk copy (UBLKCP) — kills the LDGSTS issue wall
__device__ __forceinline__ void bulkcp(uint32_t dst, const void* src, uint32_t bytes,
                                       uint32_t mbar) {
    asm volatile(
        "cp.async.bulk.shared::cluster.global.mbarrier::complete_tx::bytes "
        "[%0], [%1], %2, [%3];"
        :: "r"(dst), "l"(src), "r"(bytes), "r"(mbar) : "memory");
}

// bf16 pack/split
__device__ __forceinline__ uint32_t pkbf(__nv_bfloat16 a, __nv_bfloat16 b) {
    uint32_t lo = (uint32_t)__bfloat16_as_ushort(a);
    uint32_t hi = (uint32_t)__bfloat16_as_ushort(b);
    return lo | (hi << 16);
}
__device__ __forceinline__ void split2(float v, __nv_bfloat16& h, __nv_bfloat16& l) {
    h = __float2bfloat16_rn(v);
    l = __float2bfloat16_rn(v - __bfloat162float(h));
}

// warp-level bf16 tensor-core mma, m16n8k16, fp32 accumulate
__device__ __forceinline__ void mma16816(float* d, uint32_t a0, uint32_t a1,
                                         uint32_t a2, uint32_t a3,
                                         uint32_t b0, uint32_t b1) {
    asm volatile(
        "mma.sync.aligned.m16n8k16.row.col.f32.bf16.bf16.f32 "
        "{%0,%1,%2,%3}, {%4,%5,%6,%7}, {%8,%9}, {%0,%1,%2,%3};"
        : "+f"(d[0]), "+f"(d[1]), "+f"(d[2]), "+f"(d[3])
        : "r"(a0), "r"(a1), "r"(a2), "r"(a3), "r"(b0), "r"(b1));
}

// ---------------------------------------------------------------------------
__global__ void k_init(float* __restrict__ outp) {
    int i = blockIdx.x * blockDim.x + threadIdx.x;
    if (i < B * VOC) {
        int b = i / VOC, v = i % VOC;
        outp[(size_t)b * TT * VOC + v] = 0.0f;
    }
    if (i < B * DHID) { g_h[0][i] = 0.0f; g_h[1][i] = 0.0f; g_c[i] = 0.0f; }
}

// ---------------------------------------------------------------------------
// Repack fc_W [VOC][KFC] into bf16 hi/lo B-fragments (fragment-ordered). Once.
// ---------------------------------------------------------------------------
__global__ void __launch_bounds__(256) k_wprep(const float* __restrict__ W) {
    __shared__ float ws[64][17];
    int c = blockIdx.y, ng = blockIdx.x;
    int k0 = c * 16, n0g = ng * 64;
    int tid = threadIdx.x;

    for (int idx = tid; idx < 64 * 16; idx += 256) {
        int r = idx >> 4, q = idx & 15;
        int kg = k0 + q;
        ws[r][q] = (kg < KFC) ? W[(size_t)(n0g + r) * KFC + kg] : 0.0f;
    }
    __syncthreads();

    int ntl = tid >> 5;
    int l = tid & 31;
    int g = l >> 2, t4 = l & 3;
    int nr = ntl * 8 + g;
    float v0 = ws[nr][2 * t4], v1 = ws[nr][2 * t4 + 1];
    float v2 = ws[nr][2 * t4 + 8], v3 = ws[nr][2 * t4 + 9];
    __nv_bfloat16 h0, l0, h1, l1, h2, l2, h3, l3;
    split2(v0, h0, l0); split2(v1, h1, l1);
    split2(v2, h2, l2); split2(v3, h3, l3);
    uint4 o;
    o.x = pkbf(h0, h1); o.y = pkbf(h2, h3);
    o.z = pkbf(l0, l1); o.w = pkbf(l2, l3);
    int nt = ng * 8 + ntl;
    g_wfrag[((size_t)c * NTILES + nt) * 32 + l] = o;
}

// ---------------------------------------------------------------------------
// enc_proj (once)
// ---------------------------------------------------------------------------
__global__ void __launch_bounds__(128) k_encproj(const float* __restrict__ enc,
                                                 const float* __restrict__ attn_W,
                                                 const float* __restrict__ attn_b) {
    __shared__ __align__(16) float es[32 * 8];
    int j = threadIdx.x;
    int row0 = blockIdx.x * 32;
    float acc[32];
    float bj = attn_b[j];
#pragma unroll
    for (int r = 0; r < 32; r++) acc[r] = bj;
    const float* Wenc = attn_W + DHID * DHID;

    for (int k0 = 0; k0 < EHID; k0 += 8) {
        __syncthreads();
        int i0 = j;
        es[i0] = enc[(size_t)(row0 + (i0 >> 3)) * EHID + k0 + (i0 & 7)];
        int i1 = j + 128;
        es[i1] = enc[(size_t)(row0 + (i1 >> 3)) * EHID + k0 + (i1 & 7)];
        __syncthreads();
        float w[8];
#pragma unroll
        for (int kk = 0; kk < 8; kk++) w[kk] = Wenc[(size_t)(k0 + kk) * DHID + j];
#pragma unroll
        for (int r = 0; r < 32; r++) {
            const float4* e4 = (const float4*)(es + r * 8);
            float4 e0 = e4[0], e1 = e4[1];
            acc[r] = fmaf(e0.x, w[0], acc[r]); acc[r] = fmaf(e0.y, w[1], acc[r]);
            acc[r] = fmaf(e0.z, w[2], acc[r]); acc[r] = fmaf(e0.w, w[3], acc[r]);
            acc[r] = fmaf(e1.x, w[4], acc[r]); acc[r] = fmaf(e1.y, w[5], acc[r]);
            acc[r] = fmaf(e1.z, w[6], acc[r]); acc[r] = fmaf(e1.w, w[7], acc[r]);
        }
    }
#pragma unroll
    for (int r = 0; r < 32; r++)
        g_enc_proj[(size_t)(row0 + r) * DHID + j] = acc[r];
}

// ---------------------------------------------------------------------------
// Per-step raw scores, wide: grid (8, B), 128 threads. Block covers 32 s.
// Also emb gather (sb==0 blocks).
// ---------------------------------------------------------------------------
__global__ void __launch_bounds__(128) k_score2(
    const int* __restrict__ trg, const float* __restrict__ embt,
    const float* __restrict__ attn_W, const float* __restrict__ attn_v, int t)
{
    int sb = blockIdx.x, b = blockIdx.y;
    int tid = threadIdx.x;
    __shared__ float sh_h[DHID], sh_hp[DHID], sh_v[DHID];

    sh_h[tid] = g_h[t & 1][b * DHID + tid];
    sh_v[tid] = attn_v[tid];
    __syncthreads();

    float accp = 0.0f;
#pragma unroll 8
    for (int k = 0; k < DHID; k++)
        accp = fmaf(sh_h[k], attn_W[k * DHID + tid], accp);
    sh_hp[tid] = accp;
    __syncthreads();

    int w = tid >> 5, lane = tid & 31;
    const float* epb = g_enc_proj + (size_t)b * S * DHID;
    float hp0 = sh_hp[lane],      hp1 = sh_hp[lane + 32];
    float hp2 = sh_hp[lane + 64], hp3 = sh_hp[lane + 96];
    float v0 = sh_v[lane],        v1 = sh_v[lane + 32];
    float v2 = sh_v[lane + 64],   v3 = sh_v[lane + 96];
#pragma unroll
    for (int i = 0; i < 8; i++) {
        int s = sb * 32 + w * 8 + i;
        const float* ep = epb + (size_t)s * DHID;
        float acc = tanhfast(ep[lane]      + hp0) * v0
                  + tanhfast(ep[lane + 32] + hp1) * v1
                  + tanhfast(ep[lane + 64] + hp2) * v2
                  + tanhfast(ep[lane + 96] + hp3) * v3;
#pragma unroll
        for (int o = 16; o > 0; o >>= 1)
            acc += __shfl_xor_sync(0xFFFFFFFFu, acc, o);
        if (lane == 0) g_scr[b * S + s] = acc;
    }

    if (sb == 0) {
        int tok = trg[b * TT + t];
        for (int d = tid; d < EMBD; d += 128)
            g_xcatT[(DHID + EHID + d) * B + b] = embt[(size_t)tok * EMBD + d];
    }
}

// ---------------------------------------------------------------------------
// Per-step context with fused softmax: grid (6, 32), 128 threads.
// ---------------------------------------------------------------------------
__global__ void __launch_bounds__(128) k_ctx(const float* __restrict__ enc) {
    int tid = threadIdx.x;
    int d = blockIdx.x * 128 + tid;
    int b = blockIdx.y;
    __shared__ float sa[S];
    __shared__ float red[128];

    float r0 = g_scr[b * S + tid], r1 = g_scr[b * S + tid + 128];
    red[tid] = fmaxf(r0, r1);
    __syncthreads();
    for (int off = 64; off > 0; off >>= 1) {
        if (tid < off) red[tid] = fmaxf(red[tid], red[tid + off]);
        __syncthreads();
    }
    float mx = red[0];
    __syncthreads();
    float e0 = __expf(r0 - mx), e1 = __expf(r1 - mx);
    red[tid] = e0 + e1;
    __syncthreads();
    for (int off = 64; off > 0; off >>= 1) {
        if (tid < off) red[tid] += red[tid + off];
        __syncthreads();
    }
    float inv = __fdividef(1.0f, red[0]);
    sa[tid] = e0 * inv;
    sa[tid + 128] = e1 * inv;
    __syncthreads();

    const float* e = enc + (size_t)b * S * EHID + d;
    float a[8];
#pragma unroll
    for (int j = 0; j < 8; j++) a[j] = 0.0f;
#pragma unroll 4
    for (int s = 0; s < S; s += 8) {
#pragma unroll
        for (int j = 0; j < 8; j++)
            a[j] = fmaf(sa[s + j], e[(size_t)(s + j) * EHID], a[j]);
    }
    float r = ((a[0] + a[1]) + (a[2] + a[3])) + ((a[4] + a[5]) + (a[6] + a[7]));
    g_xcatT[(DHID + d) * B + b] = r;                      // FC x rows 128..895
}

// ---------------------------------------------------------------------------
// Per-step LSTM, 2-way k-split: grid = 128 blocks, 256 threads.
// ---------------------------------------------------------------------------
__global__ void __launch_bounds__(256) k_lstm(
    const float* __restrict__ W_ih, const float* __restrict__ W_hh,
    const float* __restrict__ b_ih, const float* __restrict__ b_hh, int t)
{
    int col = blockIdx.x;
    int tid = threadIdx.x;
    int half = tid >> 7;
    int gate = (tid >> 5) & 3;
    int b = tid & 31;
    int g = gate * DHID + col;

    __shared__ float sh_hold[32 * 129];
    __shared__ float sg[8][32];

    const float* hold = g_h[t & 1];
    for (int i = tid; i < B * DHID; i += 256)
        sh_hold[(i >> 7) * 129 + (i & 127)] = hold[i];
    __syncthreads();

    const float* Wg = W_ih + (size_t)g * KLSTM;
    float a0 = 0.f, a1 = 0.f, a2 = 0.f, a3 = 0.f;
    if (half == 0) {
        a0 = b_ih[g] + b_hh[g];
        const float* xe = g_xcatT + 896 * B + b;
#pragma unroll 2
        for (int k = 0; k < 200; k += 4) {
            float4 w = *(const float4*)(Wg + k);
            a0 = fmaf(w.x, xe[(k + 0) * B], a0);
            a1 = fmaf(w.y, xe[(k + 1) * B], a1);
            a2 = fmaf(w.z, xe[(k + 2) * B], a2);
            a3 = fmaf(w.w, xe[(k + 3) * B], a3);
        }
        const float* xw = g_xcatT - 72 * B + b;
#pragma unroll 2
        for (int k = 200; k < 484; k += 4) {
            float4 w = *(const float4*)(Wg + k);
            a0 = fmaf(w.x, xw[(k + 0) * B], a0);
            a1 = fmaf(w.y, xw[(k + 1) * B], a1);
            a2 = fmaf(w.z, xw[(k + 2) * B], a2);
            a3 = fmaf(w.w, xw[(k + 3) * B], a3);
        }
    } else {
        const float* xw = g_xcatT - 72 * B + b;
#pragma unroll 2
        for (int k = 484; k < 968; k += 4) {
            float4 w = *(const float4*)(Wg + k);
            a0 = fmaf(w.x, xw[(k + 0) * B], a0);
            a1 = fmaf(w.y, xw[(k + 1) * B], a1);
            a2 = fmaf(w.z, xw[(k + 2) * B], a2);
            a3 = fmaf(w.w, xw[(k + 3) * B], a3);
        }
        const float* Wh = W_hh + (size_t)g * DHID;
        const float* hb = sh_hold + b * 129;
#pragma unroll 4
        for (int k = 0; k < DHID; k += 4) {
            float4 w = *(const float4*)(Wh + k);
            a0 = fmaf(w.x, hb[k + 0], a0);
            a1 = fmaf(w.y, hb[k + 1], a1);
            a2 = fmaf(w.z, hb[k + 2], a2);
            a3 = fmaf(w.w, hb[k + 3], a3);
        }
    }
    sg[half * 4 + gate][b] = (a0 + a1) + (a2 + a3);
    __syncthreads();

    if (tid < 32) {
        float gi = sg[0][b] + sg[4][b];
        float gf = sg[1][b] + sg[5][b];
        float gg = sg[2][b] + sg[6][b];
        float go = sg[3][b] + sg[7][b];
        float c = g_c[b * DHID + col];
        c = sigfast(gf) * c + sigfast(gi) * tanhfast(gg);
        float h = sigfast(go) * tanhfast(c);
        g_c[b * DHID + col] = c;
        g_h[(t + 1) & 1][b * DHID + col] = h;
        g_xcatT[col * B + b] = h;
    }
}

// ---------------------------------------------------------------------------
// Per-step x prep: bf16 hi/lo A-fragments + fp32 xcat history save.
// ---------------------------------------------------------------------------
__global__ void __launch_bounds__(128) k_xprep(int t) {
    __shared__ float xs[16][33];
    int c = blockIdx.x, tid = threadIdx.x;
    int k0 = c * 16;

    for (int idx = tid; idx < 512; idx += 128) {
        int kl = idx >> 5, bb = idx & 31;
        int kg = k0 + kl;
        xs[kl][bb] = (kg < KFC) ? g_xcatT[kg * B + bb] : 0.0f;
    }
    __syncthreads();

    int mt = tid >> 6;
    int l = (tid >> 1) & 31;
    int part = tid & 1;
    int g = l >> 2, t4 = l & 3;
    int b0 = mt * 16 + g;

    float v00 = xs[2 * t4][b0],     v01 = xs[2 * t4 + 1][b0];
    float v10 = xs[2 * t4][b0 + 8], v11 = xs[2 * t4 + 1][b0 + 8];
    float v20 = xs[2 * t4 + 8][b0],     v21 = xs[2 * t4 + 9][b0];
    float v30 = xs[2 * t4 + 8][b0 + 8], v31 = xs[2 * t4 + 9][b0 + 8];

    __nv_bfloat16 h00, l00, h01, l01, h10, l10, h11, l11;
    __nv_bfloat16 h20, l20, h21, l21, h30, l30, h31, l31;
    split2(v00, h00, l00); split2(v01, h01, l01);
    split2(v10, h10, l10); split2(v11, h11, l11);
    split2(v20, h20, l20); split2(v21, h21, l21);
    split2(v30, h30, l30); split2(v31, h31, l31);
    uint4 o;
    if (part == 0) {
        o.x = pkbf(h00, h01); o.y = pkbf(h10, h11);
        o.z = pkbf(h20, h21); o.w = pkbf(h30, h31);
    } else {
        o.x = pkbf(l00, l01); o.y = pkbf(l10, l11);
        o.z = pkbf(l20, l21); o.w = pkbf(l30, l31);
    }
    g_xfragA[((c * 2 + mt) * 2 + part) * 32 + l] = o;

    for (int idx = tid; idx < 512; idx += 128) {
        int i = c * 512 + idx;
        if (i < KFC * B) g_xhist[(size_t)t * (KFC * B) + i] = g_xcatT[i];
    }
}

// ---------------------------------------------------------------------------
// Per-step FC on tensor cores; weights streamed by cp.async.bulk (1 instr /
// 16KB stage — LDGSTS-issue wall removed). grid = 125 x 256 thr.
// ---------------------------------------------------------------------------
#define FC_NST 3

__global__ void __launch_bounds__(256) k_fc(const float* __restrict__ fc_b,
                                            float* __restrict__ outp, int t) {
    __shared__ __align__(16) uint4 swq[FC_NST][1024];     // 3 x 16KB
    __shared__ __align__(8) unsigned long long mbar[FC_NST];
    int tid = threadIdx.x;
    int lane = tid & 31, wrp = tid >> 5;
    int n0 = blockIdx.x * 256;
    int nt0 = blockIdx.x * 32;

    const uint4* gsrc = g_wfrag + (size_t)nt0 * 32;
    const size_t gstep = (size_t)NTILES * 32;             // uint4 per chunk
    uint32_t sb = (uint32_t)__cvta_generic_to_shared(&swq[0][0]);
    uint32_t mb = (uint32_t)__cvta_generic_to_shared(&mbar[0]);

    if (tid == 0) {
#pragma unroll
        for (int s = 0; s < FC_NST; s++) mbar_init(mb + 8 * s, 1);
    }
    __syncthreads();
    if (tid == 0) {
#pragma unroll
        for (int s = 0; s < FC_NST - 1; s++) {
            mbar_expect(mb + 8 * s, 16384);
            bulkcp(sb + s * 16384, gsrc + (size_t)s * gstep, 16384, mb + 8 * s);
        }
    }

    float acc[2][4][4];
#pragma unroll
    for (int m = 0; m < 2; m++)
#pragma unroll
        for (int i = 0; i < 4; i++)
#pragma unroll
            for (int j = 0; j < 4; j++) acc[m][i][j] = 0.0f;

    for (int c = 0; c < NCH; c++) {
        int slot = c % FC_NST;
        // issue chunk c+2 into its (free) slot before blocking on slot c
        if (tid == 0) {
            int ns = c + FC_NST - 1;
            if (ns < NCH) {
                int s2 = ns % FC_NST;
                mbar_expect(mb + 8 * s2, 16384);
                bulkcp(sb + s2 * 16384, gsrc + (size_t)ns * gstep, 16384, mb + 8 * s2);
            }
        }
        mbar_wait(mb + 8 * slot, (c / FC_NST) & 1);

        uint4 ah0 = __ldg(&g_xfragA[((c * 2 + 0) * 2 + 0) * 32 + lane]);
        uint4 ah1 = __ldg(&g_xfragA[((c * 2 + 1) * 2 + 0) * 32 + lane]);
        uint4 al0 = __ldg(&g_xfragA[((c * 2 + 0) * 2 + 1) * 32 + lane]);
        uint4 al1 = __ldg(&g_xfragA[((c * 2 + 1) * 2 + 1) * 32 + lane]);

        const uint4* wbuf = swq[slot] + wrp * 4 * 32;
#pragma unroll
        for (int i = 0; i < 4; i++) {
            uint4 bq = wbuf[i * 32 + lane];               // {b0h,b1h,b0l,b1l}
            mma16816(acc[0][i], ah0.x, ah0.y, ah0.z, ah0.w, bq.x, bq.y);
            mma16816(acc[1][i], ah1.x, ah1.y, ah1.z, ah1.w, bq.x, bq.y);
            mma16816(acc[0][i], al0.x, al0.y, al0.z, al0.w, bq.x, bq.y);
            mma16816(acc[1][i], al1.x, al1.y, al1.z, al1.w, bq.x, bq.y);
            mma16816(acc[0][i], ah0.x, ah0.y, ah0.z, ah0.w, bq.z, bq.w);
            mma16816(acc[1][i], ah1.x, ah1.y, ah1.z, ah1.w, bq.z, bq.w);
        }
        __syncthreads();     // slot fully consumed before it gets re-filled
    }

    int g = lane >> 2, t4 = lane & 3;
#pragma unroll
    for (int m = 0; m < 2; m++) {
#pragma unroll
        for (int i = 0; i < 4; i++) {
            int n = n0 + (wrp * 4 + i) * 8 + 2 * t4;
            float b0 = fc_b[n], b1 = fc_b[n + 1];
            int br = m * 16 + g;
            size_t o1 = ((size_t)br * TT + (t + 1)) * VOC + n;
            size_t o2 = ((size_t)(br + 8) * TT + (t + 1)) * VOC + n;
            outp[o1]     = acc[m][i][0] + b0;
            outp[o1 + 1] = acc[m][i][1] + b1;
            outp[o2]     = acc[m][i][2] + b0;
            outp[o2 + 1] = acc[m][i][3] + b1;
        }
    }
}

// ---------------------------------------------------------------------------
// Epilogue argmax: approx top-2 scan + exact fp32 recompute of candidates.
// ---------------------------------------------------------------------------
__global__ void __launch_bounds__(256) k_argmax(const float* __restrict__ outp,
                                                const float* __restrict__ fc_W,
                                                const float* __restrict__ fc_b,
                                                float* __restrict__ tokout) {
    int row = blockIdx.x;            // b*TT + tt
    int b = row / TT, tt = row % TT;
    int tid = threadIdx.x;
    if (tt == 0) { if (tid == 0) tokout[row] = 0.0f; return; }

    const float* p = outp + ((size_t)b * TT + tt) * VOC;
    __shared__ float sv[256];
    __shared__ int si[256];
    __shared__ float dre[2];

    float best = -1e30f; int bi = 0;
    for (int i = tid; i < VOC; i += 256) {
        float v = p[i];
        if (v > best) { best = v; bi = i; }
    }
    sv[tid] = best; si[tid] = bi;
    __syncthreads();
    for (int off = 128; off > 0; off >>= 1) {
        if (tid < off) {
            if (sv[tid + off] > sv[tid] ||
                (sv[tid + off] == sv[tid] && si[tid + off] < si[tid])) {
                sv[tid] = sv[tid + off]; si[tid] = si[tid + off];
            }
        }
        __syncthreads();
    }
    int i1 = si[0];
    __syncthreads();

    best = -1e30f; bi = 0;
    for (int i = tid; i < VOC; i += 256) {
        if (i == i1) continue;
        float v = p[i];
        if (v > best) { best = v; bi = i; }
    }
    sv[tid] = best; si[tid] = bi;
    __syncthreads();
    for (int off = 128; off > 0; off >>= 1) {
        if (tid < off) {
            if (sv[tid + off] > sv[tid] ||
                (sv[tid + off] == sv[tid] && si[tid + off] < si[tid])) {
                sv[tid] = sv[tid + off]; si[tid] = si[tid + off];
            }
        }
        __syncthreads();
    }
    int i2 = si[0];
    __syncthreads();

    int wrp = tid >> 5, lane = tid & 31;
    if (wrp < 2) {
        int idx = (wrp == 0) ? i1 : i2;
        const float* wr = fc_W + (size_t)idx * KFC;
        const float* xr = g_xhist + (size_t)(tt - 1) * (KFC * B);
        float a = 0.0f;
        for (int k = lane; k < KFC; k += 32)
            a = fmaf(xr[k * B + b], wr[k], a);
#pragma unroll
        for (int o = 16; o > 0; o >>= 1)
            a += __shfl_xor_sync(0xFFFFFFFFu, a, o);
        if (lane == 0) dre[wrp] = a + fc_b[idx];
    }
    __syncthreads();
    if (tid == 0) {
        float d1 = dre[0], d2 = dre[1];
        int winner = i1;
        if (d2 > d1 || (d2 == d1 && i2 < i1)) winner = i2;
        tokout[row] = (float)winner;
    }
}

// ---------------------------------------------------------------------------
extern "C" void kernel_launch(void* const* d_in, const int* in_sizes, int n_in,
                              void* d_out, int out_size) {
    const float* enc    = (const float*)d_in[0];
    const int*   trg    = (const int*)d_in[1];
    const float* embt   = (const float*)d_in[2];
    const float* attn_W = (const float*)d_in[3];
    const float* attn_b = (const float*)d_in[4];
    const float* attn_v = (const float*)d_in[5];
    const float* W_ih   = (const float*)d_in[6];
    const float* W_hh   = (const float*)d_in[7];
    const float* b_ih   = (const float*)d_in[8];
    const float* b_hh   = (const float*)d_in[9];
    const float* fc_W   = (const float*)d_in[10];
    const float* fc_b   = (const float*)d_in[11];
    float* outp = (float*)d_out;
    (void)in_sizes; (void)n_in;

    k_init<<<(B * VOC + 255) / 256, 256>>>(outp);
    k_wprep<<<dim3(NTILES / 8, NCH), 256>>>(fc_W);
    k_encproj<<<(B * S) / 32, 128>>>(enc, attn_W, attn_b);

    for (int t = 0; t < NSTEP; t++) {
        k_score2<<<dim3(8, B), 128>>>(trg, embt, attn_W, attn_v, t);
        k_ctx<<<dim3(EHID / 128, B), 128>>>(enc);
        k_lstm<<<DHID, 256>>>(W_ih, W_hh, b_ih, b_hh, t);
        k_xprep<<<NCH, 128>>>(t);
        k_fc<<<VOC / 256, 256>>>(fc_b, outp, t);
    }

    long long need = (long long)B * TT * VOC + (long long)B * TT;
    if ((long long)out_size >= need) {
        k_argmax<<<B * TT, 256>>>(outp, fc_W, fc_b,
                                  outp + (size_t)B * TT * VOC);
    }
}

// round 12
// speedup vs baseline: 2.1925x; 1.1026x over previous
#include <cuda_runtime.h>
#include <cuda_bf16.h>
#include <math.h>
#include <stdint.h>

// Problem dims
#define B 32
#define S 256
#define EHID 768
#define DHID 128
#define EMBD 200
#define VOC 32000
#define TT 96
#define NSTEP 95
#define KFC 1096    // DHID + EHID + EMBD
#define KLSTM 968   // EMBD + EHID
#define NCH16 70    // k-chunks of 16 (padded: 68 full + partial + zero)
#define NCH32 35    // k-chunks of 32
#define NTILES 4000 // VOC/8 n-tiles of 8

// Scratch (static device globals: allowed; no runtime allocation)
__device__ uint4  g_wfrag[(size_t)NCH16 * NTILES * 32]; // bf16 hi/lo B-frags, ~143MB
__device__ uint4  g_xfragA[NCH16 * 2 * 2 * 32];         // [c16][mt][hi/lo][lane]
__device__ float  g_enc_proj[B * S * DHID];
__device__ float  g_xcatT[KFC * B];
__device__ float  g_xhist[NSTEP * KFC * B];             // fp32 history for exact argmax
__device__ float  g_scr[B * S];
__device__ float  g_h[2][B * DHID];
__device__ float  g_c[B * DHID];

// fast activations (validated across rounds)
__device__ __forceinline__ float sigfast(float x) {
    return __fdividef(1.0f, 1.0f + __expf(-x));
}
__device__ __forceinline__ float tanhfast(float x) {
    x = fminf(fmaxf(x, -15.0f), 15.0f);
    float e = __expf(2.0f * x);
    return __fdividef(e - 1.0f, e + 1.0f);
}

// mbarrier + bulk-copy helpers (proven R10)
__device__ __forceinline__ void mbar_init(uint32_t a, uint32_t cnt) {
    asm volatile("mbarrier.init.shared.b64 [%0], %1;" :: "r"(a), "r"(cnt) : "memory");
}
__device__ __forceinline__ void mbar_expect(uint32_t a, uint32_t bytes) {
    asm volatile("mbarrier.arrive.expect_tx.shared.b64 _, [%0], %1;"
                 :: "r"(a), "r"(bytes) : "memory");
}
__device__ __forceinline__ void mbar_wait(uint32_t a, uint32_t parity) {
    uint32_t done;
    asm volatile(
        "{\n\t.reg .pred p;\n\t"
        "mbarrier.try_wait.parity.acquire.cta.shared::cta.b64 p, [%1], %2;\n\t"
        "selp.b32 %0, 1, 0, p;\n\t}"
        : "=r"(done) : "r"(a), "r"(parity) : "memory");
    if (!done) {
        asm volatile(
            "{\n\t.reg .pred P1;\n\t"
            "W_%=:\n\t"
            "mbarrier.try_wait.parity.acquire.cta.shared::cta.b64 P1, [%0], %1, 0x989680;\n\t"
            "@P1 bra.uni D_%=;\n\t"
            "bra.uni W_%=;\n\t"
            "D_%=:\n\t}"
            :: "r"(a), "r"(parity) : "memory");
    }
}
__device__ __forceinline__ void bulkcp(uint32_t dst, const void* src, uint32_t bytes,
                                       uint32_t mbar) {
    asm volatile(
        "cp.async.bulk.shared::cluster.global.mbarrier::complete_tx::bytes "
        "[%0], [%1], %2, [%3];"
        :: "r"(dst), "l"(src), "r"(bytes), "r"(mbar) : "memory");
}

// bf16 pack/split
__device__ __forceinline__ uint32_t pkbf(__nv_bfloat16 a, __nv_bfloat16 b) {
    uint32_t lo = (uint32_t)__bfloat16_as_ushort(a);
    uint32_t hi = (uint32_t)__bfloat16_as_ushort(b);
    return lo | (hi << 16);
}
__device__ __forceinline__ void split2(float v, __nv_bfloat16& h, __nv_bfloat16& l) {
    h = __float2bfloat16_rn(v);
    l = __float2bfloat16_rn(v - __bfloat162float(h));
}

// warp-level bf16 tensor-core mma, m16n8k16, fp32 accumulate
__device__ __forceinline__ void mma16816(float* d, uint32_t a0, uint32_t a1,
                                         uint32_t a2, uint32_t a3,
                                         uint32_t b0, uint32_t b1) {
    asm volatile(
        "mma.sync.aligned.m16n8k16.row.col.f32.bf16.bf16.f32 "
        "{%0,%1,%2,%3}, {%4,%5,%6,%7}, {%8,%9}, {%0,%1,%2,%3};"
        : "+f"(d[0]), "+f"(d[1]), "+f"(d[2]), "+f"(d[3])
        : "r"(a0), "r"(a1), "r"(a2), "r"(a3), "r"(b0), "r"(b1));
}

// ---------------------------------------------------------------------------
__global__ void k_init(float* __restrict__ outp) {
    int i = blockIdx.x * blockDim.x + threadIdx.x;
    if (i < B * VOC) {
        int b = i / VOC, v = i % VOC;
        outp[(size_t)b * TT * VOC + v] = 0.0f;
    }
    if (i < B * DHID) { g_h[0][i] = 0.0f; g_h[1][i] = 0.0f; g_c[i] = 0.0f; }
}

// ---------------------------------------------------------------------------
// Repack fc_W [VOC][KFC] into bf16 hi/lo B-fragments (fragment-ordered). Once.
// grid = (500, NCH16), 256 threads.
// ---------------------------------------------------------------------------
__global__ void __launch_bounds__(256) k_wprep(const float* __restrict__ W) {
    __shared__ float ws[64][17];
    int c = blockIdx.y, ng = blockIdx.x;
    int k0 = c * 16, n0g = ng * 64;
    int tid = threadIdx.x;

    for (int idx = tid; idx < 64 * 16; idx += 256) {
        int r = idx >> 4, q = idx & 15;
        int kg = k0 + q;
        ws[r][q] = (kg < KFC) ? W[(size_t)(n0g + r) * KFC + kg] : 0.0f;
    }
    __syncthreads();

    int ntl = tid >> 5;
    int l = tid & 31;
    int g = l >> 2, t4 = l & 3;
    int nr = ntl * 8 + g;
    float v0 = ws[nr][2 * t4], v1 = ws[nr][2 * t4 + 1];
    float v2 = ws[nr][2 * t4 + 8], v3 = ws[nr][2 * t4 + 9];
    __nv_bfloat16 h0, l0, h1, l1, h2, l2, h3, l3;
    split2(v0, h0, l0); split2(v1, h1, l1);
    split2(v2, h2, l2); split2(v3, h3, l3);
    uint4 o;
    o.x = pkbf(h0, h1); o.y = pkbf(h2, h3);
    o.z = pkbf(l0, l1); o.w = pkbf(l2, l3);
    int nt = ng * 8 + ntl;
    g_wfrag[((size_t)c * NTILES + nt) * 32 + l] = o;
}

// ---------------------------------------------------------------------------
// enc_proj (once)
// ---------------------------------------------------------------------------
__global__ void __launch_bounds__(128) k_encproj(const float* __restrict__ enc,
                                                 const float* __restrict__ attn_W,
                                                 const float* __restrict__ attn_b) {
    __shared__ __align__(16) float es[32 * 8];
    int j = threadIdx.x;
    int row0 = blockIdx.x * 32;
    float acc[32];
    float bj = attn_b[j];
#pragma unroll
    for (int r = 0; r < 32; r++) acc[r] = bj;
    const float* Wenc = attn_W + DHID * DHID;

    for (int k0 = 0; k0 < EHID; k0 += 8) {
        __syncthreads();
        int i0 = j;
        es[i0] = enc[(size_t)(row0 + (i0 >> 3)) * EHID + k0 + (i0 & 7)];
        int i1 = j + 128;
        es[i1] = enc[(size_t)(row0 + (i1 >> 3)) * EHID + k0 + (i1 & 7)];
        __syncthreads();
        float w[8];
#pragma unroll
        for (int kk = 0; kk < 8; kk++) w[kk] = Wenc[(size_t)(k0 + kk) * DHID + j];
#pragma unroll
        for (int r = 0; r < 32; r++) {
            const float4* e4 = (const float4*)(es + r * 8);
            float4 e0 = e4[0], e1 = e4[1];
            acc[r] = fmaf(e0.x, w[0], acc[r]); acc[r] = fmaf(e0.y, w[1], acc[r]);
            acc[r] = fmaf(e0.z, w[2], acc[r]); acc[r] = fmaf(e0.w, w[3], acc[r]);
            acc[r] = fmaf(e1.x, w[4], acc[r]); acc[r] = fmaf(e1.y, w[5], acc[r]);
            acc[r] = fmaf(e1.z, w[6], acc[r]); acc[r] = fmaf(e1.w, w[7], acc[r]);
        }
    }
#pragma unroll
    for (int r = 0; r < 32; r++)
        g_enc_proj[(size_t)(row0 + r) * DHID + j] = acc[r];
}

// ---------------------------------------------------------------------------
// Per-step raw scores, extra-wide: grid (16, B) = 512 blocks, 128 threads.
// ---------------------------------------------------------------------------
__global__ void __launch_bounds__(128) k_score2(
    const int* __restrict__ trg, const float* __restrict__ embt,
    const float* __restrict__ attn_W, const float* __restrict__ attn_v, int t)
{
    int sb = blockIdx.x, b = blockIdx.y;
    int tid = threadIdx.x;
    __shared__ float sh_h[DHID], sh_hp[DHID], sh_v[DHID];

    sh_h[tid] = g_h[t & 1][b * DHID + tid];
    sh_v[tid] = attn_v[tid];
    __syncthreads();

    float accp = 0.0f;
#pragma unroll 8
    for (int k = 0; k < DHID; k++)
        accp = fmaf(sh_h[k], attn_W[k * DHID + tid], accp);
    sh_hp[tid] = accp;
    __syncthreads();

    int w = tid >> 5, lane = tid & 31;
    const float* epb = g_enc_proj + (size_t)b * S * DHID;
    float hp0 = sh_hp[lane],      hp1 = sh_hp[lane + 32];
    float hp2 = sh_hp[lane + 64], hp3 = sh_hp[lane + 96];
    float v0 = sh_v[lane],        v1 = sh_v[lane + 32];
    float v2 = sh_v[lane + 64],   v3 = sh_v[lane + 96];
#pragma unroll
    for (int i = 0; i < 4; i++) {
        int s = sb * 16 + w * 4 + i;
        const float* ep = epb + (size_t)s * DHID;
        float acc = tanhfast(ep[lane]      + hp0) * v0
                  + tanhfast(ep[lane + 32] + hp1) * v1
                  + tanhfast(ep[lane + 64] + hp2) * v2
                  + tanhfast(ep[lane + 96] + hp3) * v3;
#pragma unroll
        for (int o = 16; o > 0; o >>= 1)
            acc += __shfl_xor_sync(0xFFFFFFFFu, acc, o);
        if (lane == 0) g_scr[b * S + s] = acc;
    }

    if (sb == 0) {
        int tok = trg[b * TT + t];
        for (int d = tid; d < EMBD; d += 128)
            g_xcatT[(DHID + EHID + d) * B + b] = embt[(size_t)tok * EMBD + d];
    }
}

// ---------------------------------------------------------------------------
// Per-step context with fused softmax: grid (6, 32), 128 threads.
// ---------------------------------------------------------------------------
__global__ void __launch_bounds__(128) k_ctx(const float* __restrict__ enc) {
    int tid = threadIdx.x;
    int d = blockIdx.x * 128 + tid;
    int b = blockIdx.y;
    __shared__ float sa[S];
    __shared__ float red[128];

    float r0 = g_scr[b * S + tid], r1 = g_scr[b * S + tid + 128];
    red[tid] = fmaxf(r0, r1);
    __syncthreads();
    for (int off = 64; off > 0; off >>= 1) {
        if (tid < off) red[tid] = fmaxf(red[tid], red[tid + off]);
        __syncthreads();
    }
    float mx = red[0];
    __syncthreads();
    float e0 = __expf(r0 - mx), e1 = __expf(r1 - mx);
    red[tid] = e0 + e1;
    __syncthreads();
    for (int off = 64; off > 0; off >>= 1) {
        if (tid < off) red[tid] += red[tid + off];
        __syncthreads();
    }
    float inv = __fdividef(1.0f, red[0]);
    sa[tid] = e0 * inv;
    sa[tid + 128] = e1 * inv;
    __syncthreads();

    const float* e = enc + (size_t)b * S * EHID + d;
    float a[8];
#pragma unroll
    for (int j = 0; j < 8; j++) a[j] = 0.0f;
#pragma unroll 4
    for (int s = 0; s < S; s += 8) {
#pragma unroll
        for (int j = 0; j < 8; j++)
            a[j] = fmaf(sa[s + j], e[(size_t)(s + j) * EHID], a[j]);
    }
    float r = ((a[0] + a[1]) + (a[2] + a[3])) + ((a[4] + a[5]) + (a[6] + a[7]));
    g_xcatT[(DHID + d) * B + b] = r;
}

// ---------------------------------------------------------------------------
// Per-step LSTM, 2-way k-split: grid = 128 blocks, 256 threads.
// ---------------------------------------------------------------------------
__global__ void __launch_bounds__(256) k_lstm(
    const float* __restrict__ W_ih, const float* __restrict__ W_hh,
    const float* __restrict__ b_ih, const float* __restrict__ b_hh, int t)
{
    int col = blockIdx.x;
    int tid = threadIdx.x;
    int half = tid >> 7;
    int gate = (tid >> 5) & 3;
    int b = tid & 31;
    int g = gate * DHID + col;

    __shared__ float sh_hold[32 * 129];
    __shared__ float sg[8][32];

    const float* hold = g_h[t & 1];
    for (int i = tid; i < B * DHID; i += 256)
        sh_hold[(i >> 7) * 129 + (i & 127)] = hold[i];
    __syncthreads();

    const float* Wg = W_ih + (size_t)g * KLSTM;
    float a0 = 0.f, a1 = 0.f, a2 = 0.f, a3 = 0.f;
    if (half == 0) {
        a0 = b_ih[g] + b_hh[g];
        const float* xe = g_xcatT + 896 * B + b;
#pragma unroll 2
        for (int k = 0; k < 200; k += 4) {
            float4 w = *(const float4*)(Wg + k);
            a0 = fmaf(w.x, xe[(k + 0) * B], a0);
            a1 = fmaf(w.y, xe[(k + 1) * B], a1);
            a2 = fmaf(w.z, xe[(k + 2) * B], a2);
            a3 = fmaf(w.w, xe[(k + 3) * B], a3);
        }
        const float* xw = g_xcatT - 72 * B + b;
#pragma unroll 2
        for (int k = 200; k < 484; k += 4) {
            float4 w = *(const float4*)(Wg + k);
            a0 = fmaf(w.x, xw[(k + 0) * B], a0);
            a1 = fmaf(w.y, xw[(k + 1) * B], a1);
            a2 = fmaf(w.z, xw[(k + 2) * B], a2);
            a3 = fmaf(w.w, xw[(k + 3) * B], a3);
        }
    } else {
        const float* xw = g_xcatT - 72 * B + b;
#pragma unroll 2
        for (int k = 484; k < 968; k += 4) {
            float4 w = *(const float4*)(Wg + k);
            a0 = fmaf(w.x, xw[(k + 0) * B], a0);
            a1 = fmaf(w.y, xw[(k + 1) * B], a1);
            a2 = fmaf(w.z, xw[(k + 2) * B], a2);
            a3 = fmaf(w.w, xw[(k + 3) * B], a3);
        }
        const float* Wh = W_hh + (size_t)g * DHID;
        const float* hb = sh_hold + b * 129;
#pragma unroll 4
        for (int k = 0; k < DHID; k += 4) {
            float4 w = *(const float4*)(Wh + k);
            a0 = fmaf(w.x, hb[k + 0], a0);
            a1 = fmaf(w.y, hb[k + 1], a1);
            a2 = fmaf(w.z, hb[k + 2], a2);
            a3 = fmaf(w.w, hb[k + 3], a3);
        }
    }
    sg[half * 4 + gate][b] = (a0 + a1) + (a2 + a3);
    __syncthreads();

    if (tid < 32) {
        float gi = sg[0][b] + sg[4][b];
        float gf = sg[1][b] + sg[5][b];
        float gg = sg[2][b] + sg[6][b];
        float go = sg[3][b] + sg[7][b];
        float c = g_c[b * DHID + col];
        c = sigfast(gf) * c + sigfast(gi) * tanhfast(gg);
        float h = sigfast(go) * tanhfast(c);
        g_c[b * DHID + col] = c;
        g_h[(t + 1) & 1][b * DHID + col] = h;
        g_xcatT[col * B + b] = h;
    }
}

// ---------------------------------------------------------------------------
// Per-step x prep: bf16 hi/lo A-fragments + fp32 xcat history save.
// grid = NCH16, 128 threads.
// ---------------------------------------------------------------------------
__global__ void __launch_bounds__(128) k_xprep(int t) {
    __shared__ float xs[16][33];
    int c = blockIdx.x, tid = threadIdx.x;
    int k0 = c * 16;

    for (int idx = tid; idx < 512; idx += 128) {
        int kl = idx >> 5, bb = idx & 31;
        int kg = k0 + kl;
        xs[kl][bb] = (kg < KFC) ? g_xcatT[kg * B + bb] : 0.0f;
    }
    __syncthreads();

    int mt = tid >> 6;
    int l = (tid >> 1) & 31;
    int part = tid & 1;
    int g = l >> 2, t4 = l & 3;
    int b0 = mt * 16 + g;

    float v00 = xs[2 * t4][b0],     v01 = xs[2 * t4 + 1][b0];
    float v10 = xs[2 * t4][b0 + 8], v11 = xs[2 * t4 + 1][b0 + 8];
    float v20 = xs[2 * t4 + 8][b0],     v21 = xs[2 * t4 + 9][b0];
    float v30 = xs[2 * t4 + 8][b0 + 8], v31 = xs[2 * t4 + 9][b0 + 8];

    __nv_bfloat16 h00, l00, h01, l01, h10, l10, h11, l11;
    __nv_bfloat16 h20, l20, h21, l21, h30, l30, h31, l31;
    split2(v00, h00, l00); split2(v01, h01, l01);
    split2(v10, h10, l10); split2(v11, h11, l11);
    split2(v20, h20, l20); split2(v21, h21, l21);
    split2(v30, h30, l30); split2(v31, h31, l31);
    uint4 o;
    if (part == 0) {
        o.x = pkbf(h00, h01); o.y = pkbf(h10, h11);
        o.z = pkbf(h20, h21); o.w = pkbf(h30, h31);
    } else {
        o.x = pkbf(l00, l01); o.y = pkbf(l10, l11);
        o.z = pkbf(l20, l21); o.w = pkbf(l30, l31);
    }
    g_xfragA[((c * 2 + mt) * 2 + part) * 32 + l] = o;

    for (int idx = tid; idx < 512; idx += 128) {
        int kg = k0 + (idx >> 5);
        int bb = idx & 31;
        if (kg < KFC)
            g_xhist[(size_t)t * (KFC * B) + kg * B + bb] = g_xcatT[kg * B + bb];
    }
}

// ---------------------------------------------------------------------------
// Per-step FC on tensor cores (mma.sync bf16, 3-term split).
// K=32 chunks (35): half the barrier count of R10. 3-stage x 32KB bulkcp
// pipeline (dynamic smem 96KB, 1 CTA/SM). A-frags double-buffered in regs,
// prefetched BEFORE the stage wait. grid = 125 x 256 thr.
// ---------------------------------------------------------------------------
#define FC_SMEM (3 * 32768)

// load A fragments (8 uint4) for chunk32 c into dst[ksub*4 + mt*2 + part]
#define LOADA(dst, c) do {                                                     \
    int cc0 = (c) * 2;                                                         \
    dst[0] = __ldg(&g_xfragA[((cc0 * 2 + 0) * 2 + 0) * 32 + lane]);            \
    dst[1] = __ldg(&g_xfragA[((cc0 * 2 + 0) * 2 + 1) * 32 + lane]);            \
    dst[2] = __ldg(&g_xfragA[((cc0 * 2 + 1) * 2 + 0) * 32 + lane]);            \
    dst[3] = __ldg(&g_xfragA[((cc0 * 2 + 1) * 2 + 1) * 32 + lane]);            \
    dst[4] = __ldg(&g_xfragA[(((cc0 + 1) * 2 + 0) * 2 + 0) * 32 + lane]);      \
    dst[5] = __ldg(&g_xfragA[(((cc0 + 1) * 2 + 0) * 2 + 1) * 32 + lane]);      \
    dst[6] = __ldg(&g_xfragA[(((cc0 + 1) * 2 + 1) * 2 + 0) * 32 + lane]);      \
    dst[7] = __ldg(&g_xfragA[(((cc0 + 1) * 2 + 1) * 2 + 1) * 32 + lane]);      \
} while (0)

// consume one chunk32 staged at swq + slot*2048 (uint4 units), frags in af[8]
#define MMACHUNK(af, slot) do {                                                \
    _Pragma("unroll")                                                          \
    for (int ksub = 0; ksub < 2; ksub++) {                                     \
        uint4 ah0 = af[ksub * 4 + 0], al0 = af[ksub * 4 + 1];                  \
        uint4 ah1 = af[ksub * 4 + 2], al1 = af[ksub * 4 + 3];                  \
        const uint4* wbuf = swq + (slot) * 2048 + ksub * 1024 + wrp * 128;     \
        _Pragma("unroll")                                                      \
        for (int i = 0; i < 4; i++) {                                          \
            uint4 bq = wbuf[i * 32 + lane];                                    \
            mma16816(acc[0][i], ah0.x, ah0.y, ah0.z, ah0.w, bq.x, bq.y);       \
            mma16816(acc[1][i], ah1.x, ah1.y, ah1.z, ah1.w, bq.x, bq.y);       \
            mma16816(acc[0][i], al0.x, al0.y, al0.z, al0.w, bq.x, bq.y);       \
            mma16816(acc[1][i], al1.x, al1.y, al1.z, al1.w, bq.x, bq.y);       \
            mma16816(acc[0][i], ah0.x, ah0.y, ah0.z, ah0.w, bq.z, bq.w);       \
            mma16816(acc[1][i], ah1.x, ah1.y, ah1.z, ah1.w, bq.z, bq.w);       \
        }                                                                      \
    }                                                                          \
} while (0)

// issue the two 16KB bulk copies for chunk32 c into its slot (tid 0 only)
#define ISSUE(c) do {                                                          \
    int s2 = (c) % 3;                                                          \
    uint32_t sd = sb + s2 * 32768u;                                            \
    mbar_expect(mb + 8 * s2, 32768u);                                          \
    bulkcp(sd,          g_wfrag + ((size_t)(2 * (c))     * NTILES + nt0) * 32, \
           16384u, mb + 8 * s2);                                               \
    bulkcp(sd + 16384u, g_wfrag + ((size_t)(2 * (c) + 1) * NTILES + nt0) * 32, \
           16384u, mb + 8 * s2);                                               \
} while (0)

__global__ void __launch_bounds__(256) k_fc(const float* __restrict__ fc_b,
                                            float* __restrict__ outp, int t) {
    extern __shared__ __align__(16) uint4 swq[];          // 3 x 32KB
    __shared__ __align__(8) unsigned long long mbar_st[3];
    int tid = threadIdx.x;
    int lane = tid & 31, wrp = tid >> 5;
    int n0 = blockIdx.x * 256;
    int nt0 = blockIdx.x * 32;

    uint32_t sb = (uint32_t)__cvta_generic_to_shared(&swq[0]);
    uint32_t mb = (uint32_t)__cvta_generic_to_shared(&mbar_st[0]);

    if (tid == 0) {
#pragma unroll
        for (int s = 0; s < 3; s++) mbar_init(mb + 8 * s, 1);
    }
    __syncthreads();
    if (tid == 0) { ISSUE(0); ISSUE(1); }

    float acc[2][4][4];
#pragma unroll
    for (int m = 0; m < 2; m++)
#pragma unroll
        for (int i = 0; i < 4; i++)
#pragma unroll
            for (int j = 0; j < 4; j++) acc[m][i][j] = 0.0f;

    uint4 afA[8], afB[8];
    LOADA(afA, 0);

    for (int c = 0; c < NCH32; c += 2) {
        // chunk c (frags in afA)
        if (c + 1 < NCH32) LOADA(afB, c + 1);             // prefetch before wait
        mbar_wait(mb + 8 * (c % 3), (uint32_t)((c / 3) & 1));
        MMACHUNK(afA, c % 3);
        __syncthreads();
        if (tid == 0 && c + 2 < NCH32) ISSUE(c + 2);

        // chunk c+1 (frags in afB)
        if (c + 1 < NCH32) {
            if (c + 2 < NCH32) LOADA(afA, c + 2);
            mbar_wait(mb + 8 * ((c + 1) % 3), (uint32_t)(((c + 1) / 3) & 1));
            MMACHUNK(afB, (c + 1) % 3);
            __syncthreads();
            if (tid == 0 && c + 3 < NCH32) ISSUE(c + 3);
        }
    }

    // epilogue: D frag c0:D[g][2t] c1:D[g][2t+1] c2:D[g+8][2t] c3:D[g+8][2t+1]
    int g = lane >> 2, t4 = lane & 3;
#pragma unroll
    for (int m = 0; m < 2; m++) {
#pragma unroll
        for (int i = 0; i < 4; i++) {
            int n = n0 + (wrp * 4 + i) * 8 + 2 * t4;
            float b0 = fc_b[n], b1 = fc_b[n + 1];
            int br = m * 16 + g;
            size_t o1 = ((size_t)br * TT + (t + 1)) * VOC + n;
            size_t o2 = ((size_t)(br + 8) * TT + (t + 1)) * VOC + n;
            outp[o1]     = acc[m][i][0] + b0;
            outp[o1 + 1] = acc[m][i][1] + b1;
            outp[o2]     = acc[m][i][2] + b0;
            outp[o2 + 1] = acc[m][i][3] + b1;
        }
    }
}

// ---------------------------------------------------------------------------
// Epilogue argmax: approx top-2 scan + exact fp32 recompute of candidates.
// ---------------------------------------------------------------------------
__global__ void __launch_bounds__(256) k_argmax(const float* __restrict__ outp,
                                                const float* __restrict__ fc_W,
                                                const float* __restrict__ fc_b,
                                                float* __restrict__ tokout) {
    int row = blockIdx.x;
    int b = row / TT, tt = row % TT;
    int tid = threadIdx.x;
    if (tt == 0) { if (tid == 0) tokout[row] = 0.0f; return; }

    const float* p = outp + ((size_t)b * TT + tt) * VOC;
    __shared__ float sv[256];
    __shared__ int si[256];
    __shared__ float dre[2];

    float best = -1e30f; int bi = 0;
    for (int i = tid; i < VOC; i += 256) {
        float v = p[i];
        if (v > best) { best = v; bi = i; }
    }
    sv[tid] = best; si[tid] = bi;
    __syncthreads();
    for (int off = 128; off > 0; off >>= 1) {
        if (tid < off) {
            if (sv[tid + off] > sv[tid] ||
                (sv[tid + off] == sv[tid] && si[tid + off] < si[tid])) {
                sv[tid] = sv[tid + off]; si[tid] = si[tid + off];
            }
        }
        __syncthreads();
    }
    int i1 = si[0];
    __syncthreads();

    best = -1e30f; bi = 0;
    for (int i = tid; i < VOC; i += 256) {
        if (i == i1) continue;
        float v = p[i];
        if (v > best) { best = v; bi = i; }
    }
    sv[tid] = best; si[tid] = bi;
    __syncthreads();
    for (int off = 128; off > 0; off >>= 1) {
        if (tid < off) {
            if (sv[tid + off] > sv[tid] ||
                (sv[tid + off] == sv[tid] && si[tid + off] < si[tid])) {
                sv[tid] = sv[tid + off]; si[tid] = si[tid + off];
            }
        }
        __syncthreads();
    }
    int i2 = si[0];
    __syncthreads();

    int wrp = tid >> 5, lane = tid & 31;
    if (wrp < 2) {
        int idx = (wrp == 0) ? i1 : i2;
        const float* wr = fc_W + (size_t)idx * KFC;
        const float* xr = g_xhist + (size_t)(tt - 1) * (KFC * B);
        float a = 0.0f;
        for (int k = lane; k < KFC; k += 32)
            a = fmaf(xr[k * B + b], wr[k], a);
#pragma unroll
        for (int o = 16; o > 0; o >>= 1)
            a += __shfl_xor_sync(0xFFFFFFFFu, a, o);
        if (lane == 0) dre[wrp] = a + fc_b[idx];
    }
    __syncthreads();
    if (tid == 0) {
        float d1 = dre[0], d2 = dre[1];
        int winner = i1;
        if (d2 > d1 || (d2 == d1 && i2 < i1)) winner = i2;
        tokout[row] = (float)winner;
    }
}

// ---------------------------------------------------------------------------
extern "C" void kernel_launch(void* const* d_in, const int* in_sizes, int n_in,
                              void* d_out, int out_size) {
    const float* enc    = (const float*)d_in[0];
    const int*   trg    = (const int*)d_in[1];
    const float* embt   = (const float*)d_in[2];
    const float* attn_W = (const float*)d_in[3];
    const float* attn_b = (const float*)d_in[4];
    const float* attn_v = (const float*)d_in[5];
    const float* W_ih   = (const float*)d_in[6];
    const float* W_hh   = (const float*)d_in[7];
    const float* b_ih   = (const float*)d_in[8];
    const float* b_hh   = (const float*)d_in[9];
    const float* fc_W   = (const float*)d_in[10];
    const float* fc_b   = (const float*)d_in[11];
    float* outp = (float*)d_out;
    (void)in_sizes; (void)n_in;

    cudaFuncSetAttribute(k_fc, cudaFuncAttributeMaxDynamicSharedMemorySize, FC_SMEM);

    k_init<<<(B * VOC + 255) / 256, 256>>>(outp);
    k_wprep<<<dim3(NTILES / 8, NCH16), 256>>>(fc_W);
    k_encproj<<<(B * S) / 32, 128>>>(enc, attn_W, attn_b);

    for (int t = 0; t < NSTEP; t++) {
        k_score2<<<dim3(16, B), 128>>>(trg, embt, attn_W, attn_v, t);
        k_ctx<<<dim3(EHID / 128, B), 128>>>(enc);
        k_lstm<<<DHID, 256>>>(W_ih, W_hh, b_ih, b_hh, t);
        k_xprep<<<NCH16, 128>>>(t);
        k_fc<<<VOC / 256, 256, FC_SMEM>>>(fc_b, outp, t);
    }

    long long need = (long long)B * TT * VOC + (long long)B * TT;
    if ((long long)out_size >= need) {
        k_argmax<<<B * TT, 256>>>(outp, fc_W, fc_b,
                                  outp + (size_t)B * TT * VOC);
    }
}

// round 13
// speedup vs baseline: 2.4313x; 1.1089x over previous
#include <cuda_runtime.h>
#include <cuda_bf16.h>
#include <math.h>
#include <stdint.h>

// Problem dims
#define B 32
#define S 256
#define EHID 768
#define DHID 128
#define EMBD 200
#define VOC 32000
#define TT 96
#define NSTEP 95
#define KFC 1096    // DHID + EHID + EMBD
#define KLSTM 968   // EMBD + EHID
#define NCH16 70    // k-chunks of 16 (padded)
#define NCH32 35    // k-chunks of 32
#define NTILES 4000 // VOC/8 n-tiles of 8

// Scratch (static device globals: allowed; no runtime allocation)
__device__ uint4  g_wfrag[(size_t)NCH16 * NTILES * 32]; // bf16 hi/lo B-frags, ~143MB
__device__ uint4  g_xfragA[2][NCH16 * 2 * 2 * 32];      // ping-pong: fc(t) reads [t&1]
                                                        // while xprep(t+1) writes [(t+1)&1]
__device__ float  g_enc_proj[B * S * DHID];
__device__ float  g_xcatT[KFC * B];
__device__ float  g_xhist[NSTEP * KFC * B];             // fp32 history for exact argmax
__device__ float  g_scr[B * S];
__device__ float  g_h[2][B * DHID];
__device__ float  g_c[B * DHID];

// fast activations (validated across rounds)
__device__ __forceinline__ float sigfast(float x) {
    return __fdividef(1.0f, 1.0f + __expf(-x));
}
__device__ __forceinline__ float tanhfast(float x) {
    x = fminf(fmaxf(x, -15.0f), 15.0f);
    float e = __expf(2.0f * x);
    return __fdividef(e - 1.0f, e + 1.0f);
}

// mbarrier + bulk-copy helpers (proven R10/R12)
__device__ __forceinline__ void mbar_init(uint32_t a, uint32_t cnt) {
    asm volatile("mbarrier.init.shared.b64 [%0], %1;" :: "r"(a), "r"(cnt) : "memory");
}
__device__ __forceinline__ void mbar_expect(uint32_t a, uint32_t bytes) {
    asm volatile("mbarrier.arrive.expect_tx.shared.b64 _, [%0], %1;"
                 :: "r"(a), "r"(bytes) : "memory");
}
__device__ __forceinline__ void mbar_wait(uint32_t a, uint32_t parity) {
    uint32_t done;
    asm volatile(
        "{\n\t.reg .pred p;\n\t"
        "mbarrier.try_wait.parity.acquire.cta.shared::cta.b64 p, [%1], %2;\n\t"
        "selp.b32 %0, 1, 0, p;\n\t}"
        : "=r"(done) : "r"(a), "r"(parity) : "memory");
    if (!done) {
        asm volatile(
            "{\n\t.reg .pred P1;\n\t"
            "W_%=:\n\t"
            "mbarrier.try_wait.parity.acquire.cta.shared::cta.b64 P1, [%0], %1, 0x989680;\n\t"
            "@P1 bra.uni D_%=;\n\t"
            "bra.uni W_%=;\n\t"
            "D_%=:\n\t}"
            :: "r"(a), "r"(parity) : "memory");
    }
}
__device__ __forceinline__ void bulkcp(uint32_t dst, const void* src, uint32_t bytes,
                                       uint32_t mbar) {
    asm volatile(
        "cp.async.bulk.shared::cluster.global.mbarrier::complete_tx::bytes "
        "[%0], [%1], %2, [%3];"
        :: "r"(dst), "l"(src), "r"(bytes), "r"(mbar) : "memory");
}

// bf16 pack/split
__device__ __forceinline__ uint32_t pkbf(__nv_bfloat16 a, __nv_bfloat16 b) {
    uint32_t lo = (uint32_t)__bfloat16_as_ushort(a);
    uint32_t hi = (uint32_t)__bfloat16_as_ushort(b);
    return lo | (hi << 16);
}
__device__ __forceinline__ void split2(float v, __nv_bfloat16& h, __nv_bfloat16& l) {
    h = __float2bfloat16_rn(v);
    l = __float2bfloat16_rn(v - __bfloat162float(h));
}

// warp-level bf16 tensor-core mma, m16n8k16, fp32 accumulate
__device__ __forceinline__ void mma16816(float* d, uint32_t a0, uint32_t a1,
                                         uint32_t a2, uint32_t a3,
                                         uint32_t b0, uint32_t b1) {
    asm volatile(
        "mma.sync.aligned.m16n8k16.row.col.f32.bf16.bf16.f32 "
        "{%0,%1,%2,%3}, {%4,%5,%6,%7}, {%8,%9}, {%0,%1,%2,%3};"
        : "+f"(d[0]), "+f"(d[1]), "+f"(d[2]), "+f"(d[3])
        : "r"(a0), "r"(a1), "r"(a2), "r"(a3), "r"(b0), "r"(b1));
}

// ---------------------------------------------------------------------------
__global__ void k_init(float* __restrict__ outp) {
    int i = blockIdx.x * blockDim.x + threadIdx.x;
    if (i < B * VOC) {
        int b = i / VOC, v = i % VOC;
        outp[(size_t)b * TT * VOC + v] = 0.0f;
    }
    if (i < B * DHID) { g_h[0][i] = 0.0f; g_h[1][i] = 0.0f; g_c[i] = 0.0f; }
}

// ---------------------------------------------------------------------------
// Repack fc_W [VOC][KFC] into bf16 hi/lo B-fragments (fragment-ordered). Once.
// ---------------------------------------------------------------------------
__global__ void __launch_bounds__(256) k_wprep(const float* __restrict__ W) {
    __shared__ float ws[64][17];
    int c = blockIdx.y, ng = blockIdx.x;
    int k0 = c * 16, n0g = ng * 64;
    int tid = threadIdx.x;

    for (int idx = tid; idx < 64 * 16; idx += 256) {
        int r = idx >> 4, q = idx & 15;
        int kg = k0 + q;
        ws[r][q] = (kg < KFC) ? W[(size_t)(n0g + r) * KFC + kg] : 0.0f;
    }
    __syncthreads();

    int ntl = tid >> 5;
    int l = tid & 31;
    int g = l >> 2, t4 = l & 3;
    int nr = ntl * 8 + g;
    float v0 = ws[nr][2 * t4], v1 = ws[nr][2 * t4 + 1];
    float v2 = ws[nr][2 * t4 + 8], v3 = ws[nr][2 * t4 + 9];
    __nv_bfloat16 h0, l0, h1, l1, h2, l2, h3, l3;
    split2(v0, h0, l0); split2(v1, h1, l1);
    split2(v2, h2, l2); split2(v3, h3, l3);
    uint4 o;
    o.x = pkbf(h0, h1); o.y = pkbf(h2, h3);
    o.z = pkbf(l0, l1); o.w = pkbf(l2, l3);
    int nt = ng * 8 + ntl;
    g_wfrag[((size_t)c * NTILES + nt) * 32 + l] = o;
}

// ---------------------------------------------------------------------------
// enc_proj (once)
// ---------------------------------------------------------------------------
__global__ void __launch_bounds__(128) k_encproj(const float* __restrict__ enc,
                                                 const float* __restrict__ attn_W,
                                                 const float* __restrict__ attn_b) {
    __shared__ __align__(16) float es[32 * 8];
    int j = threadIdx.x;
    int row0 = blockIdx.x * 32;
    float acc[32];
    float bj = attn_b[j];
#pragma unroll
    for (int r = 0; r < 32; r++) acc[r] = bj;
    const float* Wenc = attn_W + DHID * DHID;

    for (int k0 = 0; k0 < EHID; k0 += 8) {
        __syncthreads();
        int i0 = j;
        es[i0] = enc[(size_t)(row0 + (i0 >> 3)) * EHID + k0 + (i0 & 7)];
        int i1 = j + 128;
        es[i1] = enc[(size_t)(row0 + (i1 >> 3)) * EHID + k0 + (i1 & 7)];
        __syncthreads();
        float w[8];
#pragma unroll
        for (int kk = 0; kk < 8; kk++) w[kk] = Wenc[(size_t)(k0 + kk) * DHID + j];
#pragma unroll
        for (int r = 0; r < 32; r++) {
            const float4* e4 = (const float4*)(es + r * 8);
            float4 e0 = e4[0], e1 = e4[1];
            acc[r] = fmaf(e0.x, w[0], acc[r]); acc[r] = fmaf(e0.y, w[1], acc[r]);
            acc[r] = fmaf(e0.z, w[2], acc[r]); acc[r] = fmaf(e0.w, w[3], acc[r]);
            acc[r] = fmaf(e1.x, w[4], acc[r]); acc[r] = fmaf(e1.y, w[5], acc[r]);
            acc[r] = fmaf(e1.z, w[6], acc[r]); acc[r] = fmaf(e1.w, w[7], acc[r]);
        }
    }
#pragma unroll
    for (int r = 0; r < 32; r++)
        g_enc_proj[(size_t)(row0 + r) * DHID + j] = acc[r];
}

// ---------------------------------------------------------------------------
// Per-step raw scores: grid (16, B) = 512 blocks, 128 threads.
// Launched with ProgrammaticStreamSerialization (t>=1): overlaps k_fc(t-1).
// Reads only lstm(t-1)/init state — no dependency on fc(t-1).
// ---------------------------------------------------------------------------
__global__ void __launch_bounds__(128) k_score2(
    const int* __restrict__ trg, const float* __restrict__ embt,
    const float* __restrict__ attn_W, const float* __restrict__ attn_v, int t)
{
    int sb = blockIdx.x, b = blockIdx.y;
    int tid = threadIdx.x;
    __shared__ float sh_h[DHID], sh_hp[DHID], sh_v[DHID];

    sh_h[tid] = g_h[t & 1][b * DHID + tid];
    sh_v[tid] = attn_v[tid];
    __syncthreads();

    float accp = 0.0f;
#pragma unroll 8
    for (int k = 0; k < DHID; k++)
        accp = fmaf(sh_h[k], attn_W[k * DHID + tid], accp);
    sh_hp[tid] = accp;
    __syncthreads();

    int w = tid >> 5, lane = tid & 31;
    const float* epb = g_enc_proj + (size_t)b * S * DHID;
    float hp0 = sh_hp[lane],      hp1 = sh_hp[lane + 32];
    float hp2 = sh_hp[lane + 64], hp3 = sh_hp[lane + 96];
    float v0 = sh_v[lane],        v1 = sh_v[lane + 32];
    float v2 = sh_v[lane + 64],   v3 = sh_v[lane + 96];
#pragma unroll
    for (int i = 0; i < 4; i++) {
        int s = sb * 16 + w * 4 + i;
        const float* ep = epb + (size_t)s * DHID;
        float acc = tanhfast(ep[lane]      + hp0) * v0
                  + tanhfast(ep[lane + 32] + hp1) * v1
                  + tanhfast(ep[lane + 64] + hp2) * v2
                  + tanhfast(ep[lane + 96] + hp3) * v3;
#pragma unroll
        for (int o = 16; o > 0; o >>= 1)
            acc += __shfl_xor_sync(0xFFFFFFFFu, acc, o);
        if (lane == 0) g_scr[b * S + s] = acc;
    }

    if (sb == 0) {
        int tok = trg[b * TT + t];
        for (int d = tid; d < EMBD; d += 128)
            g_xcatT[(DHID + EHID + d) * B + b] = embt[(size_t)tok * EMBD + d];
    }
}

// ---------------------------------------------------------------------------
// Per-step context with fused softmax: grid (6, 32), 128 threads.
// ---------------------------------------------------------------------------
__global__ void __launch_bounds__(128) k_ctx(const float* __restrict__ enc) {
    int tid = threadIdx.x;
    int d = blockIdx.x * 128 + tid;
    int b = blockIdx.y;
    __shared__ float sa[S];
    __shared__ float red[128];

    float r0 = g_scr[b * S + tid], r1 = g_scr[b * S + tid + 128];
    red[tid] = fmaxf(r0, r1);
    __syncthreads();
    for (int off = 64; off > 0; off >>= 1) {
        if (tid < off) red[tid] = fmaxf(red[tid], red[tid + off]);
        __syncthreads();
    }
    float mx = red[0];
    __syncthreads();
    float e0 = __expf(r0 - mx), e1 = __expf(r1 - mx);
    red[tid] = e0 + e1;
    __syncthreads();
    for (int off = 64; off > 0; off >>= 1) {
        if (tid < off) red[tid] += red[tid + off];
        __syncthreads();
    }
    float inv = __fdividef(1.0f, red[0]);
    sa[tid] = e0 * inv;
    sa[tid + 128] = e1 * inv;
    __syncthreads();

    const float* e = enc + (size_t)b * S * EHID + d;
    float a[8];
#pragma unroll
    for (int j = 0; j < 8; j++) a[j] = 0.0f;
#pragma unroll 4
    for (int s = 0; s < S; s += 8) {
#pragma unroll
        for (int j = 0; j < 8; j++)
            a[j] = fmaf(sa[s + j], e[(size_t)(s + j) * EHID], a[j]);
    }
    float r = ((a[0] + a[1]) + (a[2] + a[3])) + ((a[4] + a[5]) + (a[6] + a[7]));
    g_xcatT[(DHID + d) * B + b] = r;
}

// ---------------------------------------------------------------------------
// Per-step LSTM, 2-way k-split: grid = 128 blocks, 256 threads.
// ---------------------------------------------------------------------------
__global__ void __launch_bounds__(256) k_lstm(
    const float* __restrict__ W_ih, const float* __restrict__ W_hh,
    const float* __restrict__ b_ih, const float* __restrict__ b_hh, int t)
{
    int col = blockIdx.x;
    int tid = threadIdx.x;
    int half = tid >> 7;
    int gate = (tid >> 5) & 3;
    int b = tid & 31;
    int g = gate * DHID + col;

    __shared__ float sh_hold[32 * 129];
    __shared__ float sg[8][32];

    const float* hold = g_h[t & 1];
    for (int i = tid; i < B * DHID; i += 256)
        sh_hold[(i >> 7) * 129 + (i & 127)] = hold[i];
    __syncthreads();

    const float* Wg = W_ih + (size_t)g * KLSTM;
    float a0 = 0.f, a1 = 0.f, a2 = 0.f, a3 = 0.f;
    if (half == 0) {
        a0 = b_ih[g] + b_hh[g];
        const float* xe = g_xcatT + 896 * B + b;
#pragma unroll 2
        for (int k = 0; k < 200; k += 4) {
            float4 w = *(const float4*)(Wg + k);
            a0 = fmaf(w.x, xe[(k + 0) * B], a0);
            a1 = fmaf(w.y, xe[(k + 1) * B], a1);
            a2 = fmaf(w.z, xe[(k + 2) * B], a2);
            a3 = fmaf(w.w, xe[(k + 3) * B], a3);
        }
        const float* xw = g_xcatT - 72 * B + b;
#pragma unroll 2
        for (int k = 200; k < 484; k += 4) {
            float4 w = *(const float4*)(Wg + k);
            a0 = fmaf(w.x, xw[(k + 0) * B], a0);
            a1 = fmaf(w.y, xw[(k + 1) * B], a1);
            a2 = fmaf(w.z, xw[(k + 2) * B], a2);
            a3 = fmaf(w.w, xw[(k + 3) * B], a3);
        }
    } else {
        const float* xw = g_xcatT - 72 * B + b;
#pragma unroll 2
        for (int k = 484; k < 968; k += 4) {
            float4 w = *(const float4*)(Wg + k);
            a0 = fmaf(w.x, xw[(k + 0) * B], a0);
            a1 = fmaf(w.y, xw[(k + 1) * B], a1);
            a2 = fmaf(w.z, xw[(k + 2) * B], a2);
            a3 = fmaf(w.w, xw[(k + 3) * B], a3);
        }
        const float* Wh = W_hh + (size_t)g * DHID;
        const float* hb = sh_hold + b * 129;
#pragma unroll 4
        for (int k = 0; k < DHID; k += 4) {
            float4 w = *(const float4*)(Wh + k);
            a0 = fmaf(w.x, hb[k + 0], a0);
            a1 = fmaf(w.y, hb[k + 1], a1);
            a2 = fmaf(w.z, hb[k + 2], a2);
            a3 = fmaf(w.w, hb[k + 3], a3);
        }
    }
    sg[half * 4 + gate][b] = (a0 + a1) + (a2 + a3);
    __syncthreads();

    if (tid < 32) {
        float gi = sg[0][b] + sg[4][b];
        float gf = sg[1][b] + sg[5][b];
        float gg = sg[2][b] + sg[6][b];
        float go = sg[3][b] + sg[7][b];
        float c = g_c[b * DHID + col];
        c = sigfast(gf) * c + sigfast(gi) * tanhfast(gg);
        float h = sigfast(go) * tanhfast(c);
        g_c[b * DHID + col] = c;
        g_h[(t + 1) & 1][b * DHID + col] = h;
        g_xcatT[col * B + b] = h;
    }
}

// ---------------------------------------------------------------------------
// Per-step x prep: bf16 hi/lo A-fragments (ping-pong buffer) + history save.
// ---------------------------------------------------------------------------
__global__ void __launch_bounds__(128) k_xprep(int t) {
    __shared__ float xs[16][33];
    int c = blockIdx.x, tid = threadIdx.x;
    int k0 = c * 16;
    uint4* xab = g_xfragA[t & 1];

    for (int idx = tid; idx < 512; idx += 128) {
        int kl = idx >> 5, bb = idx & 31;
        int kg = k0 + kl;
        xs[kl][bb] = (kg < KFC) ? g_xcatT[kg * B + bb] : 0.0f;
    }
    __syncthreads();

    int mt = tid >> 6;
    int l = (tid >> 1) & 31;
    int part = tid & 1;
    int g = l >> 2, t4 = l & 3;
    int b0 = mt * 16 + g;

    float v00 = xs[2 * t4][b0],     v01 = xs[2 * t4 + 1][b0];
    float v10 = xs[2 * t4][b0 + 8], v11 = xs[2 * t4 + 1][b0 + 8];
    float v20 = xs[2 * t4 + 8][b0],     v21 = xs[2 * t4 + 9][b0];
    float v30 = xs[2 * t4 + 8][b0 + 8], v31 = xs[2 * t4 + 9][b0 + 8];

    __nv_bfloat16 h00, l00, h01, l01, h10, l10, h11, l11;
    __nv_bfloat16 h20, l20, h21, l21, h30, l30, h31, l31;
    split2(v00, h00, l00); split2(v01, h01, l01);
    split2(v10, h10, l10); split2(v11, h11, l11);
    split2(v20, h20, l20); split2(v21, h21, l21);
    split2(v30, h30, l30); split2(v31, h31, l31);
    uint4 o;
    if (part == 0) {
        o.x = pkbf(h00, h01); o.y = pkbf(h10, h11);
        o.z = pkbf(h20, h21); o.w = pkbf(h30, h31);
    } else {
        o.x = pkbf(l00, l01); o.y = pkbf(l10, l11);
        o.z = pkbf(l20, l21); o.w = pkbf(l30, l31);
    }
    xab[((c * 2 + mt) * 2 + part) * 32 + l] = o;

    for (int idx = tid; idx < 512; idx += 128) {
        int kg = k0 + (idx >> 5);
        int bb = idx & 31;
        if (kg < KFC)
            g_xhist[(size_t)t * (KFC * B) + kg * B + bb] = g_xcatT[kg * B + bb];
    }
}

// ---------------------------------------------------------------------------
// Per-step FC on tensor cores (mma.sync bf16, 3-term split). K=32 chunks,
// 3-stage bulkcp pipeline, A-frags double-buffered in regs. grid = 125 x 256.
// PDL: fires launch_dependents at entry so score(t+1)... overlaps this kernel.
// ---------------------------------------------------------------------------
#define FC_SMEM (3 * 32768)

#define LOADA(dst, c) do {                                                     \
    int cc0 = (c) * 2;                                                         \
    dst[0] = __ldg(&xab[((cc0 * 2 + 0) * 2 + 0) * 32 + lane]);                 \
    dst[1] = __ldg(&xab[((cc0 * 2 + 0) * 2 + 1) * 32 + lane]);                 \
    dst[2] = __ldg(&xab[((cc0 * 2 + 1) * 2 + 0) * 32 + lane]);                 \
    dst[3] = __ldg(&xab[((cc0 * 2 + 1) * 2 + 1) * 32 + lane]);                 \
    dst[4] = __ldg(&xab[(((cc0 + 1) * 2 + 0) * 2 + 0) * 32 + lane]);           \
    dst[5] = __ldg(&xab[(((cc0 + 1) * 2 + 0) * 2 + 1) * 32 + lane]);           \
    dst[6] = __ldg(&xab[(((cc0 + 1) * 2 + 1) * 2 + 0) * 32 + lane]);           \
    dst[7] = __ldg(&xab[(((cc0 + 1) * 2 + 1) * 2 + 1) * 32 + lane]);           \
} while (0)

#define MMACHUNK(af, slot) do {                                                \
    _Pragma("unroll")                                                          \
    for (int ksub = 0; ksub < 2; ksub++) {                                     \
        uint4 ah0 = af[ksub * 4 + 0], al0 = af[ksub * 4 + 1];                  \
        uint4 ah1 = af[ksub * 4 + 2], al1 = af[ksub * 4 + 3];                  \
        const uint4* wbuf = swq + (slot) * 2048 + ksub * 1024 + wrp * 128;     \
        _Pragma("unroll")                                                      \
        for (int i = 0; i < 4; i++) {                                          \
            uint4 bq = wbuf[i * 32 + lane];                                    \
            mma16816(acc[0][i], ah0.x, ah0.y, ah0.z, ah0.w, bq.x, bq.y);       \
            mma16816(acc[1][i], ah1.x, ah1.y, ah1.z, ah1.w, bq.x, bq.y);       \
            mma16816(acc[0][i], al0.x, al0.y, al0.z, al0.w, bq.x, bq.y);       \
            mma16816(acc[1][i], al1.x, al1.y, al1.z, al1.w, bq.x, bq.y);       \
            mma16816(acc[0][i], ah0.x, ah0.y, ah0.z, ah0.w, bq.z, bq.w);       \
            mma16816(acc[1][i], ah1.x, ah1.y, ah1.z, ah1.w, bq.z, bq.w);       \
        }                                                                      \
    }                                                                          \
} while (0)

#define ISSUE(c) do {                                                          \
    int s2 = (c) % 3;                                                          \
    uint32_t sd = sb + s2 * 32768u;                                            \
    mbar_expect(mb + 8 * s2, 32768u);                                          \
    bulkcp(sd,          g_wfrag + ((size_t)(2 * (c))     * NTILES + nt0) * 32, \
           16384u, mb + 8 * s2);                                               \
    bulkcp(sd + 16384u, g_wfrag + ((size_t)(2 * (c) + 1) * NTILES + nt0) * 32, \
           16384u, mb + 8 * s2);                                               \
} while (0)

__global__ void __launch_bounds__(256) k_fc(const float* __restrict__ fc_b,
                                            float* __restrict__ outp, int t) {
    // PDL: let the next kernel (score(t+1)) launch immediately
    asm volatile("griddepcontrol.launch_dependents;" ::: "memory");

    extern __shared__ __align__(16) uint4 swq[];          // 3 x 32KB
    __shared__ __align__(8) unsigned long long mbar_st[3];
    int tid = threadIdx.x;
    int lane = tid & 31, wrp = tid >> 5;
    int n0 = blockIdx.x * 256;
    int nt0 = blockIdx.x * 32;
    const uint4* xab = g_xfragA[t & 1];

    uint32_t sb = (uint32_t)__cvta_generic_to_shared(&swq[0]);
    uint32_t mb = (uint32_t)__cvta_generic_to_shared(&mbar_st[0]);

    if (tid == 0) {
#pragma unroll
        for (int s = 0; s < 3; s++) mbar_init(mb + 8 * s, 1);
    }
    __syncthreads();
    if (tid == 0) { ISSUE(0); ISSUE(1); }

    float acc[2][4][4];
#pragma unroll
    for (int m = 0; m < 2; m++)
#pragma unroll
        for (int i = 0; i < 4; i++)
#pragma unroll
            for (int j = 0; j < 4; j++) acc[m][i][j] = 0.0f;

    uint4 afA[8], afB[8];
    LOADA(afA, 0);

    for (int c = 0; c < NCH32; c += 2) {
        if (c + 1 < NCH32) LOADA(afB, c + 1);
        mbar_wait(mb + 8 * (c % 3), (uint32_t)((c / 3) & 1));
        MMACHUNK(afA, c % 3);
        __syncthreads();
        if (tid == 0 && c + 2 < NCH32) ISSUE(c + 2);

        if (c + 1 < NCH32) {
            if (c + 2 < NCH32) LOADA(afA, c + 2);
            mbar_wait(mb + 8 * ((c + 1) % 3), (uint32_t)(((c + 1) / 3) & 1));
            MMACHUNK(afB, (c + 1) % 3);
            __syncthreads();
            if (tid == 0 && c + 3 < NCH32) ISSUE(c + 3);
        }
    }

    int g = lane >> 2, t4 = lane & 3;
#pragma unroll
    for (int m = 0; m < 2; m++) {
#pragma unroll
        for (int i = 0; i < 4; i++) {
            int n = n0 + (wrp * 4 + i) * 8 + 2 * t4;
            float b0 = fc_b[n], b1 = fc_b[n + 1];
            int br = m * 16 + g;
            size_t o1 = ((size_t)br * TT + (t + 1)) * VOC + n;
            size_t o2 = ((size_t)(br + 8) * TT + (t + 1)) * VOC + n;
            outp[o1]     = acc[m][i][0] + b0;
            outp[o1 + 1] = acc[m][i][1] + b1;
            outp[o2]     = acc[m][i][2] + b0;
            outp[o2 + 1] = acc[m][i][3] + b1;
        }
    }
}

// ---------------------------------------------------------------------------
// Epilogue argmax: approx top-2 scan + exact fp32 recompute of candidates.
// ---------------------------------------------------------------------------
__global__ void __launch_bounds__(256) k_argmax(const float* __restrict__ outp,
                                                const float* __restrict__ fc_W,
                                                const float* __restrict__ fc_b,
                                                float* __restrict__ tokout) {
    int row = blockIdx.x;
    int b = row / TT, tt = row % TT;
    int tid = threadIdx.x;
    if (tt == 0) { if (tid == 0) tokout[row] = 0.0f; return; }

    const float* p = outp + ((size_t)b * TT + tt) * VOC;
    __shared__ float sv[256];
    __shared__ int si[256];
    __shared__ float dre[2];

    float best = -1e30f; int bi = 0;
    for (int i = tid; i < VOC; i += 256) {
        float v = p[i];
        if (v > best) { best = v; bi = i; }
    }
    sv[tid] = best; si[tid] = bi;
    __syncthreads();
    for (int off = 128; off > 0; off >>= 1) {
        if (tid < off) {
            if (sv[tid + off] > sv[tid] ||
                (sv[tid + off] == sv[tid] && si[tid + off] < si[tid])) {
                sv[tid] = sv[tid + off]; si[tid] = si[tid + off];
            }
        }
        __syncthreads();
    }
    int i1 = si[0];
    __syncthreads();

    best = -1e30f; bi = 0;
    for (int i = tid; i < VOC; i += 256) {
        if (i == i1) continue;
        float v = p[i];
        if (v > best) { best = v; bi = i; }
    }
    sv[tid] = best; si[tid] = bi;
    __syncthreads();
    for (int off = 128; off > 0; off >>= 1) {
        if (tid < off) {
            if (sv[tid + off] > sv[tid] ||
                (sv[tid + off] == sv[tid] && si[tid + off] < si[tid])) {
                sv[tid] = sv[tid + off]; si[tid] = si[tid + off];
            }
        }
        __syncthreads();
    }
    int i2 = si[0];
    __syncthreads();

    int wrp = tid >> 5, lane = tid & 31;
    if (wrp < 2) {
        int idx = (wrp == 0) ? i1 : i2;
        const float* wr = fc_W + (size_t)idx * KFC;
        const float* xr = g_xhist + (size_t)(tt - 1) * (KFC * B);
        float a = 0.0f;
        for (int k = lane; k < KFC; k += 32)
            a = fmaf(xr[k * B + b], wr[k], a);
#pragma unroll
        for (int o = 16; o > 0; o >>= 1)
            a += __shfl_xor_sync(0xFFFFFFFFu, a, o);
        if (lane == 0) dre[wrp] = a + fc_b[idx];
    }
    __syncthreads();
    if (tid == 0) {
        float d1 = dre[0], d2 = dre[1];
        int winner = i1;
        if (d2 > d1 || (d2 == d1 && i2 < i1)) winner = i2;
        tokout[row] = (float)winner;
    }
}

// ---------------------------------------------------------------------------
extern "C" void kernel_launch(void* const* d_in, const int* in_sizes, int n_in,
                              void* d_out, int out_size) {
    const float* enc    = (const float*)d_in[0];
    const int*   trg    = (const int*)d_in[1];
    const float* embt   = (const float*)d_in[2];
    const float* attn_W = (const float*)d_in[3];
    const float* attn_b = (const float*)d_in[4];
    const float* attn_v = (const float*)d_in[5];
    const float* W_ih   = (const float*)d_in[6];
    const float* W_hh   = (const float*)d_in[7];
    const float* b_ih   = (const float*)d_in[8];
    const float* b_hh   = (const float*)d_in[9];
    const float* fc_W   = (const float*)d_in[10];
    const float* fc_b   = (const float*)d_in[11];
    float* outp = (float*)d_out;
    (void)in_sizes; (void)n_in;

    cudaFuncSetAttribute(k_fc, cudaFuncAttributeMaxDynamicSharedMemorySize, FC_SMEM);

    k_init<<<(B * VOC + 255) / 256, 256>>>(outp);
    k_wprep<<<dim3(NTILES / 8, NCH16), 256>>>(fc_W);
    k_encproj<<<(B * S) / 32, 128>>>(enc, attn_W, attn_b);

    for (int t = 0; t < NSTEP; t++) {
        if (t == 0) {
            // plain: must wait for k_encproj (score reads enc_proj)
            k_score2<<<dim3(16, B), 128>>>(trg, embt, attn_W, attn_v, t);
        } else {
            // PDL secondary: launches on k_fc(t-1)'s early trigger and runs
            // concurrently with it (no data dependency on fc output).
            cudaLaunchConfig_t cfg = {};
            cfg.gridDim = dim3(16, B, 1);
            cfg.blockDim = dim3(128, 1, 1);
            cfg.dynamicSmemBytes = 0;
            cfg.stream = 0;
            cudaLaunchAttribute at[1];
            at[0].id = cudaLaunchAttributeProgrammaticStreamSerialization;
            at[0].val.programmaticStreamSerializationAllowed = 1;
            cfg.attrs = at;
            cfg.numAttrs = 1;
            cudaLaunchKernelEx(&cfg, k_score2, trg, embt, attn_W, attn_v, t);
        }
        k_ctx<<<dim3(EHID / 128, B), 128>>>(enc);
        k_lstm<<<DHID, 256>>>(W_ih, W_hh, b_ih, b_hh, t);
        k_xprep<<<NCH16, 128>>>(t);
        k_fc<<<VOC / 256, 256, FC_SMEM>>>(fc_b, outp, t);
    }

    long long need = (long long)B * TT * VOC + (long long)B * TT;
    if ((long long)out_size >= need) {
        k_argmax<<<B * TT, 256>>>(outp, fc_W, fc_b,
                                  outp + (size_t)B * TT * VOC);
    }
}